// round 2
// baseline (speedup 1.0000x reference)
#include <cuda_runtime.h>
#include <math.h>

// Problem constants
#define Bz   4
#define SQL  2048
#define SKL  2048
#define Dm   1024
#define Hh   16
#define DHd  64
#define NR   (Bz*SQL)          // 8192 rows

#define NEG_BIG (-3.0e38f)

// -------- scratch (device globals; no allocation allowed) --------
__device__ float g_qp [NR*Dm];
__device__ float g_kp [NR*Dm];
__device__ float g_vp [NR*Dm];
__device__ float g_att[NR*Dm];
__device__ float g_x  [NR*Dm];
__device__ float g_y  [NR*Dm];

// ============================================================================
// SGEMM 128x128x8, fp32: C[M,N] = A[M,K] @ W[K,N] + bias,  M=8192, N=K=1024
// ============================================================================
__global__ __launch_bounds__(256) void sgemm_bias(
    const float* __restrict__ A, const float* __restrict__ W,
    const float* __restrict__ bias, float* __restrict__ C)
{
    const int K = Dm, N = Dm;
    __shared__ float As[8][128];   // A tile transposed: As[k][m]
    __shared__ float Bs[8][128];   // W tile: Bs[k][n]

    int tid = threadIdx.x;
    int bx  = blockIdx.x;          // N / 128 = 8
    int by  = blockIdx.y;          // M / 128 = 64

    int arow = tid >> 1;           // 0..127
    int acol = (tid & 1) << 2;     // 0 or 4
    int brow = tid >> 5;           // 0..7
    int bcol = (tid & 31) << 2;    // 0..124
    int ty   = tid >> 4;           // 0..15
    int tx   = tid & 15;           // 0..15

    const float* Ab = A + (size_t)(by * 128) * K;
    const float* Wb = W + bx * 128;

    float acc[8][8];
#pragma unroll
    for (int i = 0; i < 8; i++)
#pragma unroll
        for (int j = 0; j < 8; j++) acc[i][j] = 0.f;

    for (int kt = 0; kt < K; kt += 8) {
        float4 a4 = *(const float4*)(Ab + (size_t)arow * K + kt + acol);
        float4 b4 = *(const float4*)(Wb + (size_t)(kt + brow) * N + bcol);
        As[acol + 0][arow] = a4.x;
        As[acol + 1][arow] = a4.y;
        As[acol + 2][arow] = a4.z;
        As[acol + 3][arow] = a4.w;
        *(float4*)&Bs[brow][bcol] = b4;
        __syncthreads();

#pragma unroll
        for (int k = 0; k < 8; k++) {
            float4 a0 = *(float4*)&As[k][ty * 8];
            float4 a1 = *(float4*)&As[k][ty * 8 + 4];
            float4 b0 = *(float4*)&Bs[k][tx * 8];
            float4 b1 = *(float4*)&Bs[k][tx * 8 + 4];
            float ar[8] = {a0.x, a0.y, a0.z, a0.w, a1.x, a1.y, a1.z, a1.w};
            float br[8] = {b0.x, b0.y, b0.z, b0.w, b1.x, b1.y, b1.z, b1.w};
#pragma unroll
            for (int i = 0; i < 8; i++)
#pragma unroll
                for (int j = 0; j < 8; j++)
                    acc[i][j] += ar[i] * br[j];
        }
        __syncthreads();
    }

    int crow = by * 128 + ty * 8;
    int ccol = bx * 128 + tx * 8;
    float bb[8];
#pragma unroll
    for (int j = 0; j < 8; j++) bb[j] = bias[ccol + j];
#pragma unroll
    for (int i = 0; i < 8; i++) {
        float4 o0, o1;
        o0.x = acc[i][0] + bb[0]; o0.y = acc[i][1] + bb[1];
        o0.z = acc[i][2] + bb[2]; o0.w = acc[i][3] + bb[3];
        o1.x = acc[i][4] + bb[4]; o1.y = acc[i][5] + bb[5];
        o1.z = acc[i][6] + bb[6]; o1.w = acc[i][7] + bb[7];
        *(float4*)(C + (size_t)(crow + i) * N + ccol)     = o0;
        *(float4*)(C + (size_t)(crow + i) * N + ccol + 4) = o1;
    }
}

// ============================================================================
// Flash attention, fp32. Block = (q-tile 64 rows, head h, batch b).
// 256 threads = 16x16; each thread owns a 4x4 micro-tile of S and of O.
// Online softmax with running max/denominator. mask is per (b, k), int32.
// ============================================================================
#define KVP 68   // padded row stride for KVt / Pt (bank-conflict avoidance)

__global__ __launch_bounds__(256) void flash_attn(
    const float* __restrict__ qp, const float* __restrict__ kp,
    const float* __restrict__ vp, const int* __restrict__ mask,
    float* __restrict__ attn)
{
    extern __shared__ float sm[];
    float* Qt  = sm;                 // [64][64]  Qt[d*64 + r]
    float* KVt = sm + 64 * 64;       // [64][KVP] Kt[d*KVP + k] then V[k*KVP + d]
    float* Pt  = KVt + 64 * KVP;     // [64][KVP] Pt[k*KVP + r]
    __shared__ int smask[64];

    int tid = threadIdx.x;
    int b   = blockIdx.z;
    int h   = blockIdx.y;
    int q0  = blockIdx.x * 64;

    const float* Qg = qp + (size_t)(b * SQL + q0) * Dm + h * DHd;

    // load Q tile transposed: Qt[d][r]
#pragma unroll
    for (int it = 0; it < 4; it++) {
        int f = tid + it * 256;
        int row = f & 63;
        int cc  = (f >> 6) << 2;
        float4 v = *(const float4*)(Qg + (size_t)row * Dm + cc);
        Qt[(cc + 0) * 64 + row] = v.x;
        Qt[(cc + 1) * 64 + row] = v.y;
        Qt[(cc + 2) * 64 + row] = v.z;
        Qt[(cc + 3) * 64 + row] = v.w;
    }

    int ty = tid >> 4, tx = tid & 15;
    int r0 = ty << 2, c0 = tx << 2;

    float O[4][4];
    float mi[4], li[4];
#pragma unroll
    for (int i = 0; i < 4; i++) {
        mi[i] = NEG_BIG; li[i] = 0.f;
#pragma unroll
        for (int j = 0; j < 4; j++) O[i][j] = 0.f;
    }

    const float scale = 0.03125f;   // 1/sqrt(D) = 1/32

    for (int kt = 0; kt < SKL; kt += 64) {
        const float* Kg = kp + (size_t)(b * SKL + kt) * Dm + h * DHd;
        const float* Vg = vp + (size_t)(b * SKL + kt) * Dm + h * DHd;

        __syncthreads();   // previous PV reads done before overwriting KVt

        // K tile transposed: Kt[d][k]
#pragma unroll
        for (int it = 0; it < 4; it++) {
            int f = tid + it * 256;
            int row = f & 63;
            int cc  = (f >> 6) << 2;
            float4 v = *(const float4*)(Kg + (size_t)row * Dm + cc);
            KVt[(cc + 0) * KVP + row] = v.x;
            KVt[(cc + 1) * KVP + row] = v.y;
            KVt[(cc + 2) * KVP + row] = v.z;
            KVt[(cc + 3) * KVP + row] = v.w;
        }
        if (tid < 64) smask[tid] = mask[b * SKL + kt + tid];
        __syncthreads();

        // S = Q @ K^T  (4x4 per thread)
        float s[4][4];
#pragma unroll
        for (int i = 0; i < 4; i++)
#pragma unroll
            for (int j = 0; j < 4; j++) s[i][j] = 0.f;

#pragma unroll 16
        for (int kk = 0; kk < 64; kk++) {
            float4 qv = *(float4*)&Qt[kk * 64 + r0];
            float4 kv = *(float4*)&KVt[kk * KVP + c0];
            float qr[4] = {qv.x, qv.y, qv.z, qv.w};
            float kr[4] = {kv.x, kv.y, kv.z, kv.w};
#pragma unroll
            for (int i = 0; i < 4; i++)
#pragma unroll
                for (int j = 0; j < 4; j++)
                    s[i][j] += qr[i] * kr[j];
        }

        int mk[4];
#pragma unroll
        for (int j = 0; j < 4; j++) mk[j] = smask[c0 + j];

        // online softmax update + write P^T
#pragma unroll
        for (int i = 0; i < 4; i++) {
            float tm = NEG_BIG;
#pragma unroll
            for (int j = 0; j < 4; j++) {
                s[i][j] = mk[j] ? s[i][j] * scale : NEG_BIG;
                tm = fmaxf(tm, s[i][j]);
            }
#pragma unroll
            for (int off = 8; off > 0; off >>= 1)
                tm = fmaxf(tm, __shfl_xor_sync(0xffffffffu, tm, off, 16));
            float mn = fmaxf(mi[i], tm);
            float alpha = __expf(fmaxf(mi[i] - mn, -80.f));
            float rsum = 0.f;
#pragma unroll
            for (int j = 0; j < 4; j++) {
                float p = mk[j] ? __expf(s[i][j] - mn) : 0.f;
                rsum += p;
                Pt[(c0 + j) * KVP + (r0 + i)] = p;
            }
#pragma unroll
            for (int off = 8; off > 0; off >>= 1)
                rsum += __shfl_xor_sync(0xffffffffu, rsum, off, 16);
            li[i] = li[i] * alpha + rsum;
            mi[i] = mn;
#pragma unroll
            for (int j = 0; j < 4; j++) O[i][j] *= alpha;
        }

        __syncthreads();
        // V tile natural layout: V[k][d]
#pragma unroll
        for (int it = 0; it < 4; it++) {
            int f = tid + it * 256;
            int row = f & 63;
            int cc  = (f >> 6) << 2;
            float4 v = *(const float4*)(Vg + (size_t)row * Dm + cc);
            *(float4*)&KVt[row * KVP + cc] = v;
        }
        __syncthreads();

        // O += P @ V
#pragma unroll 16
        for (int k = 0; k < 64; k++) {
            float4 pv = *(float4*)&Pt[k * KVP + r0];
            float4 vv = *(float4*)&KVt[k * KVP + c0];
            float pr[4] = {pv.x, pv.y, pv.z, pv.w};
            float vr[4] = {vv.x, vv.y, vv.z, vv.w};
#pragma unroll
            for (int i = 0; i < 4; i++)
#pragma unroll
                for (int j = 0; j < 4; j++)
                    O[i][j] += pr[i] * vr[j];
        }
    }

    float* Og = attn + (size_t)(b * SQL + q0) * Dm + h * DHd;
#pragma unroll
    for (int i = 0; i < 4; i++) {
        float inv = li[i] > 0.f ? 1.f / li[i] : 0.f;
        float4 o;
        o.x = O[i][0] * inv; o.y = O[i][1] * inv;
        o.z = O[i][2] * inv; o.w = O[i][3] * inv;
        *(float4*)(Og + (size_t)(r0 + i) * Dm + c0) = o;
    }
}

// ============================================================================
// out = LayerNorm(X + (relu? relu(Y) : Y)) * g + beta, rowwise over D=1024
// ============================================================================
__global__ __launch_bounds__(256) void add_ln(
    const float* __restrict__ X, const float* __restrict__ Y,
    const float* __restrict__ g, const float* __restrict__ be,
    float* __restrict__ out, int dorelu)
{
    int row = blockIdx.x;
    int tid = threadIdx.x;
    size_t base = (size_t)row * Dm + tid * 4;

    float4 x4 = *(const float4*)(X + base);
    float4 y4 = *(const float4*)(Y + base);
    if (dorelu) {
        y4.x = fmaxf(y4.x, 0.f); y4.y = fmaxf(y4.y, 0.f);
        y4.z = fmaxf(y4.z, 0.f); y4.w = fmaxf(y4.w, 0.f);
    }
    float v[4] = {x4.x + y4.x, x4.y + y4.y, x4.z + y4.z, x4.w + y4.w};

    float s  = v[0] + v[1] + v[2] + v[3];
    float sq = v[0]*v[0] + v[1]*v[1] + v[2]*v[2] + v[3]*v[3];
#pragma unroll
    for (int off = 16; off > 0; off >>= 1) {
        s  += __shfl_xor_sync(0xffffffffu, s,  off);
        sq += __shfl_xor_sync(0xffffffffu, sq, off);
    }
    __shared__ float sh[16];
    int w = tid >> 5;
    if ((tid & 31) == 0) { sh[w] = s; sh[8 + w] = sq; }
    __syncthreads();
    s = 0.f; sq = 0.f;
#pragma unroll
    for (int i = 0; i < 8; i++) { s += sh[i]; sq += sh[8 + i]; }

    float mean = s * (1.f / 1024.f);
    float var  = fmaf(-mean, mean, sq * (1.f / 1024.f));
    float rstd = rsqrtf(var + 1e-6f);

    float4 g4 = *(const float4*)(g  + tid * 4);
    float4 b4 = *(const float4*)(be + tid * 4);
    float4 o;
    o.x = (v[0] - mean) * rstd * g4.x + b4.x;
    o.y = (v[1] - mean) * rstd * g4.y + b4.y;
    o.z = (v[2] - mean) * rstd * g4.z + b4.z;
    o.w = (v[3] - mean) * rstd * g4.w + b4.w;
    *(float4*)(out + base) = o;
}

// ============================================================================
extern "C" void kernel_launch(void* const* d_in, const int* in_sizes, int n_in,
                              void* d_out, int out_size)
{
    const float* q    = (const float*)d_in[0];
    const float* k    = (const float*)d_in[1];
    const float* v    = (const float*)d_in[2];
    const int*   mask = (const int*)d_in[3];        // bool stored as int32
    const float* Wq   = (const float*)d_in[4];
    const float* bq   = (const float*)d_in[5];
    const float* Wk   = (const float*)d_in[6];
    const float* bk   = (const float*)d_in[7];
    const float* Wv   = (const float*)d_in[8];
    const float* bv   = (const float*)d_in[9];
    const float* Wo   = (const float*)d_in[10];
    const float* bo   = (const float*)d_in[11];
    const float* g1   = (const float*)d_in[12];
    const float* b1   = (const float*)d_in[13];
    const float* g2   = (const float*)d_in[14];
    const float* b2   = (const float*)d_in[15];

    float *qp, *kp, *vp, *at, *x, *y;
    cudaGetSymbolAddress((void**)&qp, g_qp);
    cudaGetSymbolAddress((void**)&kp, g_kp);
    cudaGetSymbolAddress((void**)&vp, g_vp);
    cudaGetSymbolAddress((void**)&at, g_att);
    cudaGetSymbolAddress((void**)&x,  g_x);
    cudaGetSymbolAddress((void**)&y,  g_y);

    dim3 gg(Dm / 128, NR / 128);
    sgemm_bias<<<gg, 256>>>(q, Wq, bq, qp);
    sgemm_bias<<<gg, 256>>>(k, Wk, bk, kp);
    sgemm_bias<<<gg, 256>>>(v, Wv, bv, vp);

    size_t smem = (size_t)(64 * 64 + 2 * 64 * KVP) * sizeof(float);  // 51200 B
    cudaFuncSetAttribute(flash_attn, cudaFuncAttributeMaxDynamicSharedMemorySize,
                         (int)smem);
    flash_attn<<<dim3(SQL / 64, Hh, Bz), 256, smem>>>(qp, kp, vp, mask, at);

    add_ln<<<NR, 256>>>(qp, at, g1, b1, x, 0);

    sgemm_bias<<<gg, 256>>>(x, Wo, bo, y);

    add_ln<<<NR, 256>>>(x, y, g2, b2, (float*)d_out, 1);
}

// round 7
// speedup vs baseline: 1.3370x; 1.3370x over previous
#include <cuda_runtime.h>
#include <cuda_bf16.h>
#include <cstdint>
#include <math.h>

// Problem constants
#define Bz   4
#define SQL  2048
#define SKL  2048
#define Dm   1024
#define Hh   16
#define DHd  64
#define NR   (Bz*SQL)          // 8192 rows
#define GK   3072              // split-bf16 K' = 3*1024
#define NCHUNK 48              // GK / 64

#define NEG_BIG (-3.0e38f)

// -------- scratch (device globals; no allocation allowed) --------
__device__ float g_qp [NR*Dm];
__device__ float g_kp [NR*Dm];
__device__ float g_vp [NR*Dm];
__device__ float g_att[NR*Dm];
__device__ float g_x  [NR*Dm];
__device__ float g_y  [NR*Dm];
__device__ __nv_bfloat16 g_a2 [(size_t)NR*GK];     // split activations
__device__ __nv_bfloat16 g_w2q[(size_t)Dm*GK];     // split+transposed weights
__device__ __nv_bfloat16 g_w2k[(size_t)Dm*GK];
__device__ __nv_bfloat16 g_w2v[(size_t)Dm*GK];
__device__ __nv_bfloat16 g_w2o[(size_t)Dm*GK];

// ============================================================================
// helpers
// ============================================================================
__device__ __forceinline__ uint32_t smem_u32(const void* p) {
    uint32_t a;
    asm("{ .reg .u64 t; cvta.to.shared.u64 t, %1; cvt.u32.u64 %0, t; }"
        : "=r"(a) : "l"(p));
    return a;
}
#define CP_ASYNC16(saddr, gptr) \
    asm volatile("cp.async.cg.shared.global [%0], [%1], 16;" \
                 :: "r"(saddr), "l"(gptr))
#define CP_COMMIT() asm volatile("cp.async.commit_group;" ::: "memory")
#define CP_WAIT1()  asm volatile("cp.async.wait_group 1;" ::: "memory")
#define CP_WAIT0()  asm volatile("cp.async.wait_group 0;" ::: "memory")

#define LDMX4(r0,r1,r2,r3,addr) \
    asm volatile("ldmatrix.sync.aligned.m8n8.x4.shared.b16 {%0,%1,%2,%3}, [%4];" \
                 : "=r"(r0), "=r"(r1), "=r"(r2), "=r"(r3) : "r"(addr))

#define MMA16816(d, a, b) \
    asm volatile("mma.sync.aligned.m16n8k16.row.col.f32.bf16.bf16.f32 " \
                 "{%0,%1,%2,%3}, {%4,%5,%6,%7}, {%8,%9}, {%0,%1,%2,%3};" \
                 : "+f"((d)[0]), "+f"((d)[1]), "+f"((d)[2]), "+f"((d)[3]) \
                 : "r"((a)[0]), "r"((a)[1]), "r"((a)[2]), "r"((a)[3]), \
                   "r"((b)[0]), "r"((b)[1]))

// ============================================================================
// Split fp32 -> bf16 hi/lo.  A2[row][0:1024)=hi, [1024:2048)=lo, [2048:3072)=hi
// ============================================================================
__global__ __launch_bounds__(256) void conv_a(
    const float* __restrict__ A, __nv_bfloat16* __restrict__ A2)
{
    size_t i = (size_t)blockIdx.x * 256 + threadIdx.x;
    int row = (int)(i >> 10);
    int k   = (int)(i & 1023);
    float v = A[i];
    __nv_bfloat16 hi = __float2bfloat16(v);
    __nv_bfloat16 lo = __float2bfloat16(v - __bfloat162float(hi));
    size_t base = (size_t)row * GK;
    A2[base + k]        = hi;
    A2[base + 1024 + k] = lo;
    A2[base + 2048 + k] = hi;
}

// W[k][n] (fp32, KxN) -> Wt2[n][0:1024)=hi(k), [1024:2048)=hi(k), [2048:3072)=lo(k)
__global__ __launch_bounds__(256) void conv_w(
    const float* __restrict__ W, __nv_bfloat16* __restrict__ Wt)
{
    __shared__ float t[32][33];
    int tx = threadIdx.x, ty = threadIdx.y;          // (32, 8)
    int n0 = blockIdx.x * 32, k0 = blockIdx.y * 32;
#pragma unroll
    for (int i = 0; i < 4; i++)
        t[ty * 4 + i][tx] = W[(size_t)(k0 + ty * 4 + i) * Dm + n0 + tx];
    __syncthreads();
#pragma unroll
    for (int i = 0; i < 4; i++) {
        int n = ty * 4 + i;
        float v = t[tx][n];
        __nv_bfloat16 hi = __float2bfloat16(v);
        __nv_bfloat16 lo = __float2bfloat16(v - __bfloat162float(hi));
        size_t base = (size_t)(n0 + n) * GK;
        Wt[base + k0 + tx]        = hi;
        Wt[base + 1024 + k0 + tx] = hi;
        Wt[base + 2048 + k0 + tx] = lo;
    }
}

// ============================================================================
// mma.sync bf16 GEMM: C[8192,1024] = A' @ W'^T + bias, fp32 accum
// tile 128x128, K chunks of 64, cp.async double buffer.
// smem row stride 144B (ldmatrix conflict-free).
// ============================================================================
#define SST   144                 // bytes per 64-bf16 row (padded)
#define MATB  (128 * SST)         // 18432 B per matrix per stage
#define STAGEB (2 * MATB)         // A + B per stage
#define GEMM_SMEM (2 * STAGEB)    // 73728 B

__global__ __launch_bounds__(256) void gemm_mma(
    const __nv_bfloat16* __restrict__ A2, const __nv_bfloat16* __restrict__ B2,
    const float* __restrict__ bias, float* __restrict__ C)
{
    extern __shared__ char smem[];
    uint32_t sb = smem_u32(smem);
    int tid  = threadIdx.x;
    int wid  = tid >> 5;
    int lane = tid & 31;
    int bx = blockIdx.x;   // N tile (0..7)
    int by = blockIdx.y;   // M tile (0..63)

    int warp_m = wid >> 2;       // 0..1
    int warp_n = wid & 3;        // 0..3

    const char* gA = (const char*)(A2 + (size_t)(by * 128) * GK);
    const char* gB = (const char*)(B2 + (size_t)(bx * 128) * GK);

    // per-thread load mapping: 4 iters x 256 threads cover 128 rows x 8 x 16B
    int lrow[4], lcol[4];
#pragma unroll
    for (int it = 0; it < 4; it++) {
        int f = tid + it * 256;
        lrow[it] = f >> 3;
        lcol[it] = (f & 7) * 16;
    }

    float acc[4][4][4];
#pragma unroll
    for (int mt = 0; mt < 4; mt++)
#pragma unroll
        for (int nt = 0; nt < 4; nt++)
#pragma unroll
            for (int r = 0; r < 4; r++) acc[mt][nt][r] = 0.f;

    // prefetch chunk 0 into stage 0
    {
        uint32_t as = sb, bs = sb + MATB;
#pragma unroll
        for (int it = 0; it < 4; it++) {
            long go = (long)lrow[it] * (GK * 2) + lcol[it];
            uint32_t so = (uint32_t)(lrow[it] * SST + lcol[it]);
            CP_ASYNC16(as + so, gA + go);
            CP_ASYNC16(bs + so, gB + go);
        }
        CP_COMMIT();
    }

    for (int c = 0; c < NCHUNK; c++) {
        int st = c & 1;
        // prefetch chunk c+1 into other stage
        if (c + 1 < NCHUNK) {
            uint32_t as = sb + (st ^ 1) * STAGEB, bs = as + MATB;
#pragma unroll
            for (int it = 0; it < 4; it++) {
                long go = (long)lrow[it] * (GK * 2) + (c + 1) * 128 + lcol[it];
                uint32_t so = (uint32_t)(lrow[it] * SST + lcol[it]);
                CP_ASYNC16(as + so, gA + go);
                CP_ASYNC16(bs + so, gB + go);
            }
            CP_COMMIT();
            CP_WAIT1();
        } else {
            CP_WAIT0();
        }
        __syncthreads();

        uint32_t aS = sb + st * STAGEB;
        uint32_t bS = aS + MATB;

        int arow = warp_m * 64 + (lane & 15);
        int acol = ((lane >> 4) << 3);                 // +8 for upper half
        int brow = warp_n * 32 + (lane & 7) + ((lane >> 4) << 3);
        int bcol = (((lane >> 3) & 1) << 3);

#pragma unroll
        for (int ks = 0; ks < 4; ks++) {
            uint32_t a[4][4];
            uint32_t b[4][2];
#pragma unroll
            for (int mt = 0; mt < 4; mt++) {
                uint32_t ad = aS + (uint32_t)((arow + mt * 16) * SST
                                              + (ks * 16 + acol) * 2);
                LDMX4(a[mt][0], a[mt][1], a[mt][2], a[mt][3], ad);
            }
#pragma unroll
            for (int nh = 0; nh < 2; nh++) {
                uint32_t bd = bS + (uint32_t)((brow + nh * 16) * SST
                                              + (ks * 16 + bcol) * 2);
                LDMX4(b[nh * 2][0], b[nh * 2][1],
                      b[nh * 2 + 1][0], b[nh * 2 + 1][1], bd);
            }
#pragma unroll
            for (int mt = 0; mt < 4; mt++)
#pragma unroll
                for (int nt = 0; nt < 4; nt++)
                    MMA16816(acc[mt][nt], a[mt], b[nt]);
        }
        __syncthreads();
    }

    // epilogue: C fragment c0,c1 -> (row g, col 2tg,2tg+1); c2,c3 -> row g+8
    int g  = lane >> 2;
    int tg = lane & 3;
#pragma unroll
    for (int mt = 0; mt < 4; mt++) {
        int row = by * 128 + warp_m * 64 + mt * 16 + g;
#pragma unroll
        for (int nt = 0; nt < 4; nt++) {
            int col = bx * 128 + warp_n * 32 + nt * 8 + tg * 2;
            float2 bv = *(const float2*)(bias + col);
            float2 o0, o1;
            o0.x = acc[mt][nt][0] + bv.x;
            o0.y = acc[mt][nt][1] + bv.y;
            o1.x = acc[mt][nt][2] + bv.x;
            o1.y = acc[mt][nt][3] + bv.y;
            *(float2*)(C + (size_t)row * Dm + col)       = o0;
            *(float2*)(C + (size_t)(row + 8) * Dm + col) = o1;
        }
    }
}

// ============================================================================
// Flash attention, fp32 (unchanged from passing R2 kernel)
// ============================================================================
#define KVP 68

__global__ __launch_bounds__(256) void flash_attn(
    const float* __restrict__ qp, const float* __restrict__ kp,
    const float* __restrict__ vp, const int* __restrict__ mask,
    float* __restrict__ attn)
{
    extern __shared__ float sm[];
    float* Qt  = sm;
    float* KVt = sm + 64 * 64;
    float* Pt  = KVt + 64 * KVP;
    __shared__ int smask[64];

    int tid = threadIdx.x;
    int b   = blockIdx.z;
    int h   = blockIdx.y;
    int q0  = blockIdx.x * 64;

    const float* Qg = qp + (size_t)(b * SQL + q0) * Dm + h * DHd;

#pragma unroll
    for (int it = 0; it < 4; it++) {
        int f = tid + it * 256;
        int row = f & 63;
        int cc  = (f >> 6) << 2;
        float4 v = *(const float4*)(Qg + (size_t)row * Dm + cc);
        Qt[(cc + 0) * 64 + row] = v.x;
        Qt[(cc + 1) * 64 + row] = v.y;
        Qt[(cc + 2) * 64 + row] = v.z;
        Qt[(cc + 3) * 64 + row] = v.w;
    }

    int ty = tid >> 4, tx = tid & 15;
    int r0 = ty << 2, c0 = tx << 2;

    float O[4][4];
    float mi[4], li[4];
#pragma unroll
    for (int i = 0; i < 4; i++) {
        mi[i] = NEG_BIG; li[i] = 0.f;
#pragma unroll
        for (int j = 0; j < 4; j++) O[i][j] = 0.f;
    }

    const float scale = 0.03125f;

    for (int kt = 0; kt < SKL; kt += 64) {
        const float* Kg = kp + (size_t)(b * SKL + kt) * Dm + h * DHd;
        const float* Vg = vp + (size_t)(b * SKL + kt) * Dm + h * DHd;

        __syncthreads();

#pragma unroll
        for (int it = 0; it < 4; it++) {
            int f = tid + it * 256;
            int row = f & 63;
            int cc  = (f >> 6) << 2;
            float4 v = *(const float4*)(Kg + (size_t)row * Dm + cc);
            KVt[(cc + 0) * KVP + row] = v.x;
            KVt[(cc + 1) * KVP + row] = v.y;
            KVt[(cc + 2) * KVP + row] = v.z;
            KVt[(cc + 3) * KVP + row] = v.w;
        }
        if (tid < 64) smask[tid] = mask[b * SKL + kt + tid];
        __syncthreads();

        float s[4][4];
#pragma unroll
        for (int i = 0; i < 4; i++)
#pragma unroll
            for (int j = 0; j < 4; j++) s[i][j] = 0.f;

#pragma unroll 16
        for (int kk = 0; kk < 64; kk++) {
            float4 qv = *(float4*)&Qt[kk * 64 + r0];
            float4 kv = *(float4*)&KVt[kk * KVP + c0];
            float qr[4] = {qv.x, qv.y, qv.z, qv.w};
            float kr[4] = {kv.x, kv.y, kv.z, kv.w};
#pragma unroll
            for (int i = 0; i < 4; i++)
#pragma unroll
                for (int j = 0; j < 4; j++)
                    s[i][j] += qr[i] * kr[j];
        }

        int mk[4];
#pragma unroll
        for (int j = 0; j < 4; j++) mk[j] = smask[c0 + j];

#pragma unroll
        for (int i = 0; i < 4; i++) {
            float tm = NEG_BIG;
#pragma unroll
            for (int j = 0; j < 4; j++) {
                s[i][j] = mk[j] ? s[i][j] * scale : NEG_BIG;
                tm = fmaxf(tm, s[i][j]);
            }
#pragma unroll
            for (int off = 8; off > 0; off >>= 1)
                tm = fmaxf(tm, __shfl_xor_sync(0xffffffffu, tm, off, 16));
            float mn = fmaxf(mi[i], tm);
            float alpha = __expf(fmaxf(mi[i] - mn, -80.f));
            float rsum = 0.f;
#pragma unroll
            for (int j = 0; j < 4; j++) {
                float p = mk[j] ? __expf(s[i][j] - mn) : 0.f;
                rsum += p;
                Pt[(c0 + j) * KVP + (r0 + i)] = p;
            }
#pragma unroll
            for (int off = 8; off > 0; off >>= 1)
                rsum += __shfl_xor_sync(0xffffffffu, rsum, off, 16);
            li[i] = li[i] * alpha + rsum;
            mi[i] = mn;
#pragma unroll
            for (int j = 0; j < 4; j++) O[i][j] *= alpha;
        }

        __syncthreads();
#pragma unroll
        for (int it = 0; it < 4; it++) {
            int f = tid + it * 256;
            int row = f & 63;
            int cc  = (f >> 6) << 2;
            float4 v = *(const float4*)(Vg + (size_t)row * Dm + cc);
            *(float4*)&KVt[row * KVP + cc] = v;
        }
        __syncthreads();

#pragma unroll 16
        for (int k = 0; k < 64; k++) {
            float4 pv = *(float4*)&Pt[k * KVP + r0];
            float4 vv = *(float4*)&KVt[k * KVP + c0];
            float pr[4] = {pv.x, pv.y, pv.z, pv.w};
            float vr[4] = {vv.x, vv.y, vv.z, vv.w};
#pragma unroll
            for (int i = 0; i < 4; i++)
#pragma unroll
                for (int j = 0; j < 4; j++)
                    O[i][j] += pr[i] * vr[j];
        }
    }

    float* Og = attn + (size_t)(b * SQL + q0) * Dm + h * DHd;
#pragma unroll
    for (int i = 0; i < 4; i++) {
        float inv = li[i] > 0.f ? 1.f / li[i] : 0.f;
        float4 o;
        o.x = O[i][0] * inv; o.y = O[i][1] * inv;
        o.z = O[i][2] * inv; o.w = O[i][3] * inv;
        *(float4*)(Og + (size_t)(r0 + i) * Dm + c0) = o;
    }
}

// ============================================================================
// out = LayerNorm(X + (relu? relu(Y) : Y)) * g + beta
// ============================================================================
__global__ __launch_bounds__(256) void add_ln(
    const float* __restrict__ X, const float* __restrict__ Y,
    const float* __restrict__ g, const float* __restrict__ be,
    float* __restrict__ out, int dorelu)
{
    int row = blockIdx.x;
    int tid = threadIdx.x;
    size_t base = (size_t)row * Dm + tid * 4;

    float4 x4 = *(const float4*)(X + base);
    float4 y4 = *(const float4*)(Y + base);
    if (dorelu) {
        y4.x = fmaxf(y4.x, 0.f); y4.y = fmaxf(y4.y, 0.f);
        y4.z = fmaxf(y4.z, 0.f); y4.w = fmaxf(y4.w, 0.f);
    }
    float v[4] = {x4.x + y4.x, x4.y + y4.y, x4.z + y4.z, x4.w + y4.w};

    float s  = v[0] + v[1] + v[2] + v[3];
    float sq = v[0]*v[0] + v[1]*v[1] + v[2]*v[2] + v[3]*v[3];
#pragma unroll
    for (int off = 16; off > 0; off >>= 1) {
        s  += __shfl_xor_sync(0xffffffffu, s,  off);
        sq += __shfl_xor_sync(0xffffffffu, sq, off);
    }
    __shared__ float sh[16];
    int w = tid >> 5;
    if ((tid & 31) == 0) { sh[w] = s; sh[8 + w] = sq; }
    __syncthreads();
    s = 0.f; sq = 0.f;
#pragma unroll
    for (int i = 0; i < 8; i++) { s += sh[i]; sq += sh[8 + i]; }

    float mean = s * (1.f / 1024.f);
    float var  = fmaf(-mean, mean, sq * (1.f / 1024.f));
    float rstd = rsqrtf(var + 1e-6f);

    float4 g4 = *(const float4*)(g  + tid * 4);
    float4 b4 = *(const float4*)(be + tid * 4);
    float4 o;
    o.x = (v[0] - mean) * rstd * g4.x + b4.x;
    o.y = (v[1] - mean) * rstd * g4.y + b4.y;
    o.z = (v[2] - mean) * rstd * g4.z + b4.z;
    o.w = (v[3] - mean) * rstd * g4.w + b4.w;
    *(float4*)(out + base) = o;
}

// ============================================================================
extern "C" void kernel_launch(void* const* d_in, const int* in_sizes, int n_in,
                              void* d_out, int out_size)
{
    const float* q    = (const float*)d_in[0];
    const float* k    = (const float*)d_in[1];
    const float* v    = (const float*)d_in[2];
    const int*   mask = (const int*)d_in[3];
    const float* Wq   = (const float*)d_in[4];
    const float* bq   = (const float*)d_in[5];
    const float* Wk   = (const float*)d_in[6];
    const float* bk   = (const float*)d_in[7];
    const float* Wv   = (const float*)d_in[8];
    const float* bv   = (const float*)d_in[9];
    const float* Wo   = (const float*)d_in[10];
    const float* bo   = (const float*)d_in[11];
    const float* g1   = (const float*)d_in[12];
    const float* b1   = (const float*)d_in[13];
    const float* g2   = (const float*)d_in[14];
    const float* b2   = (const float*)d_in[15];

    float *qp, *kp, *vp, *at, *x, *y;
    __nv_bfloat16 *a2, *w2q, *w2k, *w2v, *w2o;
    cudaGetSymbolAddress((void**)&qp, g_qp);
    cudaGetSymbolAddress((void**)&kp, g_kp);
    cudaGetSymbolAddress((void**)&vp, g_vp);
    cudaGetSymbolAddress((void**)&at, g_att);
    cudaGetSymbolAddress((void**)&x,  g_x);
    cudaGetSymbolAddress((void**)&y,  g_y);
    cudaGetSymbolAddress((void**)&a2,  g_a2);
    cudaGetSymbolAddress((void**)&w2q, g_w2q);
    cudaGetSymbolAddress((void**)&w2k, g_w2k);
    cudaGetSymbolAddress((void**)&w2v, g_w2v);
    cudaGetSymbolAddress((void**)&w2o, g_w2o);

    cudaFuncSetAttribute(gemm_mma, cudaFuncAttributeMaxDynamicSharedMemorySize,
                         GEMM_SMEM);

    dim3 cwg(Dm / 32, Dm / 32);
    dim3 cwb(32, 8);
    conv_w<<<cwg, cwb>>>(Wq, w2q);
    conv_w<<<cwg, cwb>>>(Wk, w2k);
    conv_w<<<cwg, cwb>>>(Wv, w2v);
    conv_w<<<cwg, cwb>>>(Wo, w2o);

    dim3 gg(Dm / 128, NR / 128);
    int cab = (int)(((size_t)NR * Dm) / 256);

    conv_a<<<cab, 256>>>(q, a2);
    gemm_mma<<<gg, 256, GEMM_SMEM>>>(a2, w2q, bq, qp);
    conv_a<<<cab, 256>>>(k, a2);
    gemm_mma<<<gg, 256, GEMM_SMEM>>>(a2, w2k, bk, kp);
    conv_a<<<cab, 256>>>(v, a2);
    gemm_mma<<<gg, 256, GEMM_SMEM>>>(a2, w2v, bv, vp);

    size_t smem = (size_t)(64 * 64 + 2 * 64 * KVP) * sizeof(float);
    cudaFuncSetAttribute(flash_attn, cudaFuncAttributeMaxDynamicSharedMemorySize,
                         (int)smem);
    flash_attn<<<dim3(SQL / 64, Hh, Bz), 256, smem>>>(qp, kp, vp, mask, at);

    add_ln<<<NR, 256>>>(qp, at, g1, b1, x, 0);

    conv_a<<<cab, 256>>>(x, a2);
    gemm_mma<<<gg, 256, GEMM_SMEM>>>(a2, w2o, bo, y);

    add_ln<<<NR, 256>>>(x, y, g2, b2, (float*)d_out, 1);
}

// round 9
// speedup vs baseline: 3.0620x; 2.2902x over previous
#include <cuda_runtime.h>
#include <cuda_bf16.h>
#include <cstdint>
#include <math.h>

// Problem constants
#define Bz   4
#define SQL  2048
#define SKL  2048
#define Dm   1024
#define Hh   16
#define DHd  64
#define NR   (Bz*SQL)          // 8192 rows
#define GK   3072              // split-bf16 K' = 3*1024
#define NCHUNK 48              // GK / 64
#define HD2  192               // split head dim 3*64

// -------- scratch (device globals; no allocation allowed) --------
__device__ float g_qp [NR*Dm];
__device__ float g_kp [NR*Dm];
__device__ float g_vp [NR*Dm];
__device__ float g_att[NR*Dm];
__device__ float g_x  [NR*Dm];
__device__ float g_y  [NR*Dm];
__device__ __nv_bfloat16 g_a2 [(size_t)NR*GK];     // split activations (GEMM)
__device__ __nv_bfloat16 g_w2q[(size_t)Dm*GK];
__device__ __nv_bfloat16 g_w2k[(size_t)Dm*GK];
__device__ __nv_bfloat16 g_w2v[(size_t)Dm*GK];
__device__ __nv_bfloat16 g_w2o[(size_t)Dm*GK];
__device__ __nv_bfloat16 g_q2x[(size_t)Bz*Hh*SQL*HD2];
__device__ __nv_bfloat16 g_k2x[(size_t)Bz*Hh*SKL*HD2];
__device__ __nv_bfloat16 g_v2x[(size_t)Bz*Hh*SKL*DHd];
__device__ float g_mf [Bz*SKL];

// ============================================================================
// helpers
// ============================================================================
__device__ __forceinline__ uint32_t smem_u32(const void* p) {
    uint32_t a;
    asm("{ .reg .u64 t; cvta.to.shared.u64 t, %1; cvt.u32.u64 %0, t; }"
        : "=r"(a) : "l"(p));
    return a;
}
#define CP_ASYNC16(saddr, gptr) \
    asm volatile("cp.async.cg.shared.global [%0], [%1], 16;" \
                 :: "r"(saddr), "l"(gptr))
#define CP_COMMIT() asm volatile("cp.async.commit_group;" ::: "memory")
#define CP_WAIT1()  asm volatile("cp.async.wait_group 1;" ::: "memory")
#define CP_WAIT0()  asm volatile("cp.async.wait_group 0;" ::: "memory")

#define LDMX4(r0,r1,r2,r3,addr) \
    asm volatile("ldmatrix.sync.aligned.m8n8.x4.shared.b16 {%0,%1,%2,%3}, [%4];" \
                 : "=r"(r0), "=r"(r1), "=r"(r2), "=r"(r3) : "r"(addr))
#define LDMX4T(r0,r1,r2,r3,addr) \
    asm volatile("ldmatrix.sync.aligned.m8n8.x4.trans.shared.b16 {%0,%1,%2,%3}, [%4];" \
                 : "=r"(r0), "=r"(r1), "=r"(r2), "=r"(r3) : "r"(addr))

#define MMA16816(d, a, b) \
    asm volatile("mma.sync.aligned.m16n8k16.row.col.f32.bf16.bf16.f32 " \
                 "{%0,%1,%2,%3}, {%4,%5,%6,%7}, {%8,%9}, {%0,%1,%2,%3};" \
                 : "+f"((d)[0]), "+f"((d)[1]), "+f"((d)[2]), "+f"((d)[3]) \
                 : "r"((a)[0]), "r"((a)[1]), "r"((a)[2]), "r"((a)[3]), \
                   "r"((b)[0]), "r"((b)[1]))

__device__ __forceinline__ uint32_t packbf(float a, float b) {
    __nv_bfloat162 t = __floats2bfloat162_rn(a, b);
    return *(uint32_t*)&t;
}

// ============================================================================
// conversion kernels
// ============================================================================
__global__ __launch_bounds__(256) void conv_a(
    const float* __restrict__ A, __nv_bfloat16* __restrict__ A2)
{
    size_t i = (size_t)blockIdx.x * 256 + threadIdx.x;
    int row = (int)(i >> 10);
    int k   = (int)(i & 1023);
    float v = A[i];
    __nv_bfloat16 hi = __float2bfloat16(v);
    __nv_bfloat16 lo = __float2bfloat16(v - __bfloat162float(hi));
    size_t base = (size_t)row * GK;
    A2[base + k]        = hi;
    A2[base + 1024 + k] = lo;
    A2[base + 2048 + k] = hi;
}

__global__ __launch_bounds__(256) void conv_w(
    const float* __restrict__ W, __nv_bfloat16* __restrict__ Wt)
{
    __shared__ float t[32][33];
    int tx = threadIdx.x, ty = threadIdx.y;
    int n0 = blockIdx.x * 32, k0 = blockIdx.y * 32;
#pragma unroll
    for (int i = 0; i < 4; i++)
        t[ty * 4 + i][tx] = W[(size_t)(k0 + ty * 4 + i) * Dm + n0 + tx];
    __syncthreads();
#pragma unroll
    for (int i = 0; i < 4; i++) {
        int n = ty * 4 + i;
        float v = t[tx][n];
        __nv_bfloat16 hi = __float2bfloat16(v);
        __nv_bfloat16 lo = __float2bfloat16(v - __bfloat162float(hi));
        size_t base = (size_t)(n0 + n) * GK;
        Wt[base + k0 + tx]        = hi;
        Wt[base + 1024 + k0 + tx] = hi;
        Wt[base + 2048 + k0 + tx] = lo;
    }
}

// qp/kp [8192][1024] fp32 -> [(b*16+h)*2048+r][192] split bf16
// mode 0 (Q): [hi, lo, hi]   mode 1 (K): [hi, hi, lo]
__global__ __launch_bounds__(256) void conv_qk(
    const float* __restrict__ S, __nv_bfloat16* __restrict__ D, int mode)
{
    size_t i = (size_t)blockIdx.x * 256 + threadIdx.x;
    int row = (int)(i >> 10);
    int col = (int)(i & 1023);
    int b = row >> 11, r = row & 2047;
    int h = col >> 6,  d = col & 63;
    float v = S[i];
    __nv_bfloat16 hi = __float2bfloat16(v);
    __nv_bfloat16 lo = __float2bfloat16(v - __bfloat162float(hi));
    size_t base = ((size_t)((b * 16 + h) * 2048 + r)) * HD2;
    if (mode == 0) {
        D[base + d]       = hi;
        D[base + 64 + d]  = lo;
        D[base + 128 + d] = hi;
    } else {
        D[base + d]       = hi;
        D[base + 64 + d]  = hi;
        D[base + 128 + d] = lo;
    }
}

// vp -> [(b*16+h)*2048+r][64] bf16
__global__ __launch_bounds__(256) void conv_v(
    const float* __restrict__ S, __nv_bfloat16* __restrict__ D)
{
    size_t i = (size_t)blockIdx.x * 256 + threadIdx.x;
    int row = (int)(i >> 10);
    int col = (int)(i & 1023);
    int b = row >> 11, r = row & 2047;
    int h = col >> 6,  d = col & 63;
    D[((size_t)((b * 16 + h) * 2048 + r)) * DHd + d] = __float2bfloat16(S[i]);
}

__global__ __launch_bounds__(256) void conv_mask(
    const int* __restrict__ m, float* __restrict__ mf)
{
    int i = blockIdx.x * 256 + threadIdx.x;
    if (i < Bz * SKL) mf[i] = m[i] ? 1.0f : 0.0f;
}

// ============================================================================
// mma.sync bf16 GEMM (unchanged from R7)
// ============================================================================
#define SST   144
#define MATB  (128 * SST)
#define STAGEB (2 * MATB)
#define GEMM_SMEM (2 * STAGEB)

__global__ __launch_bounds__(256) void gemm_mma(
    const __nv_bfloat16* __restrict__ A2, const __nv_bfloat16* __restrict__ B2,
    const float* __restrict__ bias, float* __restrict__ C)
{
    extern __shared__ char smem[];
    uint32_t sb = smem_u32(smem);
    int tid  = threadIdx.x;
    int wid  = tid >> 5;
    int lane = tid & 31;
    int bx = blockIdx.x;
    int by = blockIdx.y;

    int warp_m = wid >> 2;
    int warp_n = wid & 3;

    const char* gA = (const char*)(A2 + (size_t)(by * 128) * GK);
    const char* gB = (const char*)(B2 + (size_t)(bx * 128) * GK);

    int lrow[4], lcol[4];
#pragma unroll
    for (int it = 0; it < 4; it++) {
        int f = tid + it * 256;
        lrow[it] = f >> 3;
        lcol[it] = (f & 7) * 16;
    }

    float acc[4][4][4];
#pragma unroll
    for (int mt = 0; mt < 4; mt++)
#pragma unroll
        for (int nt = 0; nt < 4; nt++)
#pragma unroll
            for (int r = 0; r < 4; r++) acc[mt][nt][r] = 0.f;

    {
        uint32_t as = sb, bs = sb + MATB;
#pragma unroll
        for (int it = 0; it < 4; it++) {
            long go = (long)lrow[it] * (GK * 2) + lcol[it];
            uint32_t so = (uint32_t)(lrow[it] * SST + lcol[it]);
            CP_ASYNC16(as + so, gA + go);
            CP_ASYNC16(bs + so, gB + go);
        }
        CP_COMMIT();
    }

    for (int c = 0; c < NCHUNK; c++) {
        int st = c & 1;
        if (c + 1 < NCHUNK) {
            uint32_t as = sb + (st ^ 1) * STAGEB, bs = as + MATB;
#pragma unroll
            for (int it = 0; it < 4; it++) {
                long go = (long)lrow[it] * (GK * 2) + (c + 1) * 128 + lcol[it];
                uint32_t so = (uint32_t)(lrow[it] * SST + lcol[it]);
                CP_ASYNC16(as + so, gA + go);
                CP_ASYNC16(bs + so, gB + go);
            }
            CP_COMMIT();
            CP_WAIT1();
        } else {
            CP_WAIT0();
        }
        __syncthreads();

        uint32_t aS = sb + st * STAGEB;
        uint32_t bS = aS + MATB;

        int arow = warp_m * 64 + (lane & 15);
        int acol = ((lane >> 4) << 3);
        int brow = warp_n * 32 + (lane & 7) + ((lane >> 4) << 3);
        int bcol = (((lane >> 3) & 1) << 3);

#pragma unroll
        for (int ks = 0; ks < 4; ks++) {
            uint32_t a[4][4];
            uint32_t b[4][2];
#pragma unroll
            for (int mt = 0; mt < 4; mt++) {
                uint32_t ad = aS + (uint32_t)((arow + mt * 16) * SST
                                              + (ks * 16 + acol) * 2);
                LDMX4(a[mt][0], a[mt][1], a[mt][2], a[mt][3], ad);
            }
#pragma unroll
            for (int nh = 0; nh < 2; nh++) {
                uint32_t bd = bS + (uint32_t)((brow + nh * 16) * SST
                                              + (ks * 16 + bcol) * 2);
                LDMX4(b[nh * 2][0], b[nh * 2][1],
                      b[nh * 2 + 1][0], b[nh * 2 + 1][1], bd);
            }
#pragma unroll
            for (int mt = 0; mt < 4; mt++)
#pragma unroll
                for (int nt = 0; nt < 4; nt++)
                    MMA16816(acc[mt][nt], a[mt], b[nt]);
        }
        __syncthreads();
    }

    int g  = lane >> 2;
    int tg = lane & 3;
#pragma unroll
    for (int mt = 0; mt < 4; mt++) {
        int row = by * 128 + warp_m * 64 + mt * 16 + g;
#pragma unroll
        for (int nt = 0; nt < 4; nt++) {
            int col = bx * 128 + warp_n * 32 + nt * 8 + tg * 2;
            float2 bv = *(const float2*)(bias + col);
            float2 o0, o1;
            o0.x = acc[mt][nt][0] + bv.x;
            o0.y = acc[mt][nt][1] + bv.y;
            o1.x = acc[mt][nt][2] + bv.x;
            o1.y = acc[mt][nt][3] + bv.y;
            *(float2*)(C + (size_t)row * Dm + col)       = o0;
            *(float2*)(C + (size_t)(row + 8) * Dm + col) = o1;
        }
    }
}

// ============================================================================
// Flash attention, mma.sync bf16 (unchanged from R8)
// ============================================================================
#define QROWB 400
#define VROWB 144
#define KTILEB (64 * QROWB)
#define VOFF   KTILEB
#define MOFF   (KTILEB + 64 * VROWB)
#define STGB   (MOFF + 256)
#define FLASH_SMEM (2 * STGB)

__global__ __launch_bounds__(256, 1) void flash_mma(
    const __nv_bfloat16* __restrict__ Q2, const __nv_bfloat16* __restrict__ K2,
    const __nv_bfloat16* __restrict__ V2, const float* __restrict__ MF,
    float* __restrict__ attn)
{
    extern __shared__ char smem[];
    uint32_t sb = smem_u32(smem);
    int tid  = threadIdx.x;
    int wid  = tid >> 5;
    int lane = tid & 31;
    int qx = blockIdx.x, h = blockIdx.y, b = blockIdx.z;

    size_t bh = (size_t)(b * 16 + h) * 2048;
    const char* gQ = (const char*)(Q2 + (bh + qx * 128) * HD2);
    const char* gK = (const char*)(K2 + bh * HD2);
    const char* gV = (const char*)(V2 + bh * DHd);
    const char* gM = (const char*)(MF + b * SKL);

    // ---- stage Q' into smem, then ldmatrix into registers ----
#pragma unroll
    for (int it = 0; it < 12; it++) {
        int f = tid + it * 256;
        int r = f / 24, c = f % 24;
        CP_ASYNC16(sb + r * QROWB + c * 16, gQ + (long)r * (HD2 * 2) + c * 16);
    }
    CP_COMMIT();
    CP_WAIT0();
    __syncthreads();

    uint32_t qf[12][4];
    {
        int arow = wid * 16 + (lane & 15);
        int acol = ((lane >> 4) << 3);
#pragma unroll
        for (int ks = 0; ks < 12; ks++)
            LDMX4(qf[ks][0], qf[ks][1], qf[ks][2], qf[ks][3],
                  sb + arow * QROWB + (ks * 16 + acol) * 2);
    }
    __syncthreads();

    int g  = lane >> 2;
    int tg = lane & 3;

    float O[8][4];
#pragma unroll
    for (int dt = 0; dt < 8; dt++)
#pragma unroll
        for (int r = 0; r < 4; r++) O[dt][r] = 0.f;
    float m0 = -30000.f, m1 = -30000.f, l0 = 0.f, l1 = 0.f;

    const float scale = 0.03125f;

    // prefetch ktile 0 into stage 0
#pragma unroll
    for (int it = 0; it < 6; it++) {
        int f = tid + it * 256;
        int r = f / 24, c = f % 24;
        CP_ASYNC16(sb + r * QROWB + c * 16, gK + (long)r * (HD2 * 2) + c * 16);
    }
#pragma unroll
    for (int it = 0; it < 2; it++) {
        int f = tid + it * 256;
        int r = f >> 3, c = f & 7;
        CP_ASYNC16(sb + VOFF + r * VROWB + c * 16, gV + (long)r * 128 + c * 16);
    }
    if (tid < 16) CP_ASYNC16(sb + MOFF + tid * 16, gM + tid * 16);
    CP_COMMIT();

    for (int kt = 0; kt < 32; kt++) {
        int st = kt & 1;
        if (kt + 1 < 32) {
            uint32_t ds = sb + (st ^ 1) * STGB;
            const char* nK = gK + (long)(kt + 1) * 64 * (HD2 * 2);
            const char* nV = gV + (long)(kt + 1) * 64 * 128;
#pragma unroll
            for (int it = 0; it < 6; it++) {
                int f = tid + it * 256;
                int r = f / 24, c = f % 24;
                CP_ASYNC16(ds + r * QROWB + c * 16, nK + (long)r * (HD2 * 2) + c * 16);
            }
#pragma unroll
            for (int it = 0; it < 2; it++) {
                int f = tid + it * 256;
                int r = f >> 3, c = f & 7;
                CP_ASYNC16(ds + VOFF + r * VROWB + c * 16, nV + (long)r * 128 + c * 16);
            }
            if (tid < 16)
                CP_ASYNC16(ds + MOFF + tid * 16, gM + (kt + 1) * 256 + tid * 16);
            CP_COMMIT();
            CP_WAIT1();
        } else {
            CP_WAIT0();
        }
        __syncthreads();

        uint32_t kS = sb + st * STGB;
        uint32_t vS = kS + VOFF;
        uint32_t mS = kS + MOFF;

        // ---- S = Q' K'^T ----
        float s[8][4];
#pragma unroll
        for (int nt = 0; nt < 8; nt++)
#pragma unroll
            for (int r = 0; r < 4; r++) s[nt][r] = 0.f;

        int brow = (lane & 7) + ((lane >> 4) << 3);
        int bcol = (((lane >> 3) & 1) << 3);
#pragma unroll
        for (int ks = 0; ks < 12; ks++) {
#pragma unroll
            for (int j = 0; j < 4; j++) {
                uint32_t bfr[2][2];
                LDMX4(bfr[0][0], bfr[0][1], bfr[1][0], bfr[1][1],
                      kS + (j * 16 + brow) * QROWB + (ks * 16 + bcol) * 2);
                MMA16816(s[2 * j],     qf[ks], bfr[0]);
                MMA16816(s[2 * j + 1], qf[ks], bfr[1]);
            }
        }

        // ---- softmax (online) ----
        float mf[8][2];
#pragma unroll
        for (int nt = 0; nt < 8; nt++) {
            mf[nt][0] = *(const float*)((const char*)smem + (mS - sb) + (nt * 8 + 2 * tg) * 4);
            mf[nt][1] = *(const float*)((const char*)smem + (mS - sb) + (nt * 8 + 2 * tg + 1) * 4);
        }
        float rm0 = -30000.f, rm1 = -30000.f;
#pragma unroll
        for (int nt = 0; nt < 8; nt++) {
#pragma unroll
            for (int e = 0; e < 2; e++) {
                float off = (mf[nt][e] - 1.0f) * 30000.f;
                s[nt][e]     = s[nt][e]     * scale + off;
                s[nt][2 + e] = s[nt][2 + e] * scale + off;
                rm0 = fmaxf(rm0, s[nt][e]);
                rm1 = fmaxf(rm1, s[nt][2 + e]);
            }
        }
        rm0 = fmaxf(rm0, __shfl_xor_sync(0xffffffffu, rm0, 1));
        rm0 = fmaxf(rm0, __shfl_xor_sync(0xffffffffu, rm0, 2));
        rm1 = fmaxf(rm1, __shfl_xor_sync(0xffffffffu, rm1, 1));
        rm1 = fmaxf(rm1, __shfl_xor_sync(0xffffffffu, rm1, 2));

        float mn0 = fmaxf(m0, rm0), mn1 = fmaxf(m1, rm1);
        float al0 = __expf(m0 - mn0), al1 = __expf(m1 - mn1);
        m0 = mn0; m1 = mn1;

        float rs0 = 0.f, rs1 = 0.f;
#pragma unroll
        for (int nt = 0; nt < 8; nt++) {
#pragma unroll
            for (int e = 0; e < 2; e++) {
                float p0 = __expf(s[nt][e]     - mn0) * mf[nt][e];
                float p1 = __expf(s[nt][2 + e] - mn1) * mf[nt][e];
                s[nt][e] = p0;  s[nt][2 + e] = p1;
                rs0 += p0;  rs1 += p1;
            }
        }
        rs0 += __shfl_xor_sync(0xffffffffu, rs0, 1);
        rs0 += __shfl_xor_sync(0xffffffffu, rs0, 2);
        rs1 += __shfl_xor_sync(0xffffffffu, rs1, 1);
        rs1 += __shfl_xor_sync(0xffffffffu, rs1, 2);
        l0 = l0 * al0 + rs0;
        l1 = l1 * al1 + rs1;

#pragma unroll
        for (int dt = 0; dt < 8; dt++) {
            O[dt][0] *= al0; O[dt][1] *= al0;
            O[dt][2] *= al1; O[dt][3] *= al1;
        }

        // ---- O += P V ----
        int vrow = (lane & 7) + (((lane >> 3) & 1) << 3);
        int vcol = ((lane >> 4) << 3);
#pragma unroll
        for (int ks = 0; ks < 4; ks++) {
            uint32_t pa[4];
            pa[0] = packbf(s[2 * ks][0],     s[2 * ks][1]);
            pa[1] = packbf(s[2 * ks][2],     s[2 * ks][3]);
            pa[2] = packbf(s[2 * ks + 1][0], s[2 * ks + 1][1]);
            pa[3] = packbf(s[2 * ks + 1][2], s[2 * ks + 1][3]);
#pragma unroll
            for (int j = 0; j < 4; j++) {
                uint32_t bfr[2][2];
                LDMX4T(bfr[0][0], bfr[0][1], bfr[1][0], bfr[1][1],
                       vS + (ks * 16 + vrow) * VROWB + (j * 16 + vcol) * 2);
                MMA16816(O[2 * j],     pa, bfr[0]);
                MMA16816(O[2 * j + 1], pa, bfr[1]);
            }
        }
        __syncthreads();
    }

    float inv0 = l0 > 0.f ? 1.f / l0 : 0.f;
    float inv1 = l1 > 0.f ? 1.f / l1 : 0.f;
    int row0 = qx * 128 + wid * 16 + g;
    float* oBase = attn + (size_t)(b * SQL) * Dm + h * DHd;
#pragma unroll
    for (int dt = 0; dt < 8; dt++) {
        int col = dt * 8 + 2 * tg;
        float2 o0 = {O[dt][0] * inv0, O[dt][1] * inv0};
        float2 o1 = {O[dt][2] * inv1, O[dt][3] * inv1};
        *(float2*)(oBase + (size_t)row0 * Dm + col)       = o0;
        *(float2*)(oBase + (size_t)(row0 + 8) * Dm + col) = o1;
    }
}

// ============================================================================
// out = LayerNorm(X + (relu? relu(Y) : Y)) * g + beta
// ============================================================================
__global__ __launch_bounds__(256) void add_ln(
    const float* __restrict__ X, const float* __restrict__ Y,
    const float* __restrict__ g, const float* __restrict__ be,
    float* __restrict__ out, int dorelu)
{
    int row = blockIdx.x;
    int tid = threadIdx.x;
    size_t base = (size_t)row * Dm + tid * 4;

    float4 x4 = *(const float4*)(X + base);
    float4 y4 = *(const float4*)(Y + base);
    if (dorelu) {
        y4.x = fmaxf(y4.x, 0.f); y4.y = fmaxf(y4.y, 0.f);
        y4.z = fmaxf(y4.z, 0.f); y4.w = fmaxf(y4.w, 0.f);
    }
    float v[4] = {x4.x + y4.x, x4.y + y4.y, x4.z + y4.z, x4.w + y4.w};

    float s  = v[0] + v[1] + v[2] + v[3];
    float sq = v[0]*v[0] + v[1]*v[1] + v[2]*v[2] + v[3]*v[3];
#pragma unroll
    for (int off = 16; off > 0; off >>= 1) {
        s  += __shfl_xor_sync(0xffffffffu, s,  off);
        sq += __shfl_xor_sync(0xffffffffu, sq, off);
    }
    __shared__ float sh[16];
    int w = tid >> 5;
    if ((tid & 31) == 0) { sh[w] = s; sh[8 + w] = sq; }
    __syncthreads();
    s = 0.f; sq = 0.f;
#pragma unroll
    for (int i = 0; i < 8; i++) { s += sh[i]; sq += sh[8 + i]; }

    float mean = s * (1.f / 1024.f);
    float var  = fmaf(-mean, mean, sq * (1.f / 1024.f));
    float rstd = rsqrtf(var + 1e-6f);

    float4 g4 = *(const float4*)(g  + tid * 4);
    float4 b4 = *(const float4*)(be + tid * 4);
    float4 o;
    o.x = (v[0] - mean) * rstd * g4.x + b4.x;
    o.y = (v[1] - mean) * rstd * g4.y + b4.y;
    o.z = (v[2] - mean) * rstd * g4.z + b4.z;
    o.w = (v[3] - mean) * rstd * g4.w + b4.w;
    *(float4*)(out + base) = o;
}

// ============================================================================
extern "C" void kernel_launch(void* const* d_in, const int* in_sizes, int n_in,
                              void* d_out, int out_size)
{
    const float* q    = (const float*)d_in[0];
    const float* k    = (const float*)d_in[1];
    const float* v    = (const float*)d_in[2];
    const int*   mask = (const int*)d_in[3];
    const float* Wq   = (const float*)d_in[4];
    const float* bq   = (const float*)d_in[5];
    const float* Wk   = (const float*)d_in[6];
    const float* bk   = (const float*)d_in[7];
    const float* Wv   = (const float*)d_in[8];
    const float* bv   = (const float*)d_in[9];
    const float* Wo   = (const float*)d_in[10];
    const float* bo   = (const float*)d_in[11];
    const float* g1   = (const float*)d_in[12];
    const float* b1   = (const float*)d_in[13];
    const float* g2   = (const float*)d_in[14];
    const float* b2   = (const float*)d_in[15];

    float *qp, *kp, *vp, *at, *x, *y, *mf;
    __nv_bfloat16 *a2, *w2q, *w2k, *w2v, *w2o, *q2, *k2, *v2;
    cudaGetSymbolAddress((void**)&qp, g_qp);
    cudaGetSymbolAddress((void**)&kp, g_kp);
    cudaGetSymbolAddress((void**)&vp, g_vp);
    cudaGetSymbolAddress((void**)&at, g_att);
    cudaGetSymbolAddress((void**)&x,  g_x);
    cudaGetSymbolAddress((void**)&y,  g_y);
    cudaGetSymbolAddress((void**)&a2,  g_a2);
    cudaGetSymbolAddress((void**)&w2q, g_w2q);
    cudaGetSymbolAddress((void**)&w2k, g_w2k);
    cudaGetSymbolAddress((void**)&w2v, g_w2v);
    cudaGetSymbolAddress((void**)&w2o, g_w2o);
    cudaGetSymbolAddress((void**)&q2,  g_q2x);
    cudaGetSymbolAddress((void**)&k2,  g_k2x);
    cudaGetSymbolAddress((void**)&v2,  g_v2x);
    cudaGetSymbolAddress((void**)&mf,  g_mf);

    cudaFuncSetAttribute(gemm_mma, cudaFuncAttributeMaxDynamicSharedMemorySize,
                         GEMM_SMEM);
    cudaFuncSetAttribute(flash_mma, cudaFuncAttributeMaxDynamicSharedMemorySize,
                         FLASH_SMEM);

    dim3 cwg(Dm / 32, Dm / 32);
    dim3 cwb(32, 8);
    conv_w<<<cwg, cwb>>>(Wq, w2q);
    conv_w<<<cwg, cwb>>>(Wk, w2k);
    conv_w<<<cwg, cwb>>>(Wv, w2v);
    conv_w<<<cwg, cwb>>>(Wo, w2o);

    dim3 gg(Dm / 128, NR / 128);
    int cab = (int)(((size_t)NR * Dm) / 256);

    conv_a<<<cab, 256>>>(q, a2);
    gemm_mma<<<gg, 256, GEMM_SMEM>>>(a2, w2q, bq, qp);
    conv_a<<<cab, 256>>>(k, a2);
    gemm_mma<<<gg, 256, GEMM_SMEM>>>(a2, w2k, bk, kp);
    conv_a<<<cab, 256>>>(v, a2);
    gemm_mma<<<gg, 256, GEMM_SMEM>>>(a2, w2v, bv, vp);

    conv_qk<<<cab, 256>>>(qp, q2, 0);   // Q: [hi, lo, hi]
    conv_qk<<<cab, 256>>>(kp, k2, 1);   // K: [hi, hi, lo]
    conv_v<<<cab, 256>>>(vp, v2);
    conv_mask<<<(Bz * SKL + 255) / 256, 256>>>(mask, mf);

    flash_mma<<<dim3(SQL / 128, Hh, Bz), 256, FLASH_SMEM>>>(q2, k2, v2, mf, at);

    add_ln<<<NR, 256>>>(qp, at, g1, b1, x, 0);

    conv_a<<<cab, 256>>>(x, a2);
    gemm_mma<<<gg, 256, GEMM_SMEM>>>(a2, w2o, bo, y);

    add_ln<<<NR, 256>>>(x, y, g2, b2, (float*)d_out, 1);
}

// round 10
// speedup vs baseline: 3.4001x; 1.1104x over previous
#include <cuda_runtime.h>
#include <cuda_bf16.h>
#include <cstdint>
#include <math.h>

// Problem constants
#define Bz   4
#define SQL  2048
#define SKL  2048
#define Dm   1024
#define Hh   16
#define DHd  64
#define NR   (Bz*SQL)          // 8192 rows
#define GK   3072              // split-bf16 K' = 3*1024
#define NCHUNK 48              // GK / 64
#define HD2  192               // split head dim 3*64

// -------- scratch (device globals; no allocation allowed) --------
__device__ float g_qp [NR*Dm];
__device__ float g_att[NR*Dm];
__device__ float g_x  [NR*Dm];
__device__ float g_y  [NR*Dm];
__device__ __nv_bfloat16 g_a2q[(size_t)NR*GK];
__device__ __nv_bfloat16 g_a2k[(size_t)NR*GK];
__device__ __nv_bfloat16 g_a2v[(size_t)NR*GK];
__device__ __nv_bfloat16 g_w2q[(size_t)Dm*GK];
__device__ __nv_bfloat16 g_w2k[(size_t)Dm*GK];
__device__ __nv_bfloat16 g_w2v[(size_t)Dm*GK];
__device__ __nv_bfloat16 g_w2o[(size_t)Dm*GK];
__device__ __nv_bfloat16 g_q2x[(size_t)Bz*Hh*SQL*HD2];
__device__ __nv_bfloat16 g_k2x[(size_t)Bz*Hh*SKL*HD2];
__device__ __nv_bfloat16 g_v2x[(size_t)Bz*Hh*SKL*DHd];
__device__ float g_mf [Bz*SKL];

// ============================================================================
// helpers
// ============================================================================
__device__ __forceinline__ uint32_t smem_u32(const void* p) {
    uint32_t a;
    asm("{ .reg .u64 t; cvta.to.shared.u64 t, %1; cvt.u32.u64 %0, t; }"
        : "=r"(a) : "l"(p));
    return a;
}
#define CP_ASYNC16(saddr, gptr) \
    asm volatile("cp.async.cg.shared.global [%0], [%1], 16;" \
                 :: "r"(saddr), "l"(gptr))
#define CP_COMMIT() asm volatile("cp.async.commit_group;" ::: "memory")
#define CP_WAIT2()  asm volatile("cp.async.wait_group 2;" ::: "memory")
#define CP_WAIT1()  asm volatile("cp.async.wait_group 1;" ::: "memory")
#define CP_WAIT0()  asm volatile("cp.async.wait_group 0;" ::: "memory")

#define LDMX4(r0,r1,r2,r3,addr) \
    asm volatile("ldmatrix.sync.aligned.m8n8.x4.shared.b16 {%0,%1,%2,%3}, [%4];" \
                 : "=r"(r0), "=r"(r1), "=r"(r2), "=r"(r3) : "r"(addr))
#define LDMX4T(r0,r1,r2,r3,addr) \
    asm volatile("ldmatrix.sync.aligned.m8n8.x4.trans.shared.b16 {%0,%1,%2,%3}, [%4];" \
                 : "=r"(r0), "=r"(r1), "=r"(r2), "=r"(r3) : "r"(addr))

#define MMA16816(d, a, b) \
    asm volatile("mma.sync.aligned.m16n8k16.row.col.f32.bf16.bf16.f32 " \
                 "{%0,%1,%2,%3}, {%4,%5,%6,%7}, {%8,%9}, {%0,%1,%2,%3};" \
                 : "+f"((d)[0]), "+f"((d)[1]), "+f"((d)[2]), "+f"((d)[3]) \
                 : "r"((a)[0]), "r"((a)[1]), "r"((a)[2]), "r"((a)[3]), \
                   "r"((b)[0]), "r"((b)[1]))

__device__ __forceinline__ uint32_t packbf(float a, float b) {
    __nv_bfloat162 t = __floats2bfloat162_rn(a, b);
    return *(uint32_t*)&t;
}
__device__ __forceinline__ void split1(float v, __nv_bfloat16& hi, __nv_bfloat16& lo) {
    hi = __float2bfloat16(v);
    lo = __float2bfloat16(v - __bfloat162float(hi));
}

// ============================================================================
// conversion kernels
// ============================================================================
// batched: z=0 q, z=1 k, z=2 v  -> a2 split [hi, lo, hi]
__global__ __launch_bounds__(256) void conv_a3(
    const float* __restrict__ q, const float* __restrict__ k,
    const float* __restrict__ v,
    __nv_bfloat16* __restrict__ aq, __nv_bfloat16* __restrict__ ak,
    __nv_bfloat16* __restrict__ av)
{
    int z = blockIdx.z;
    const float* A = (z == 0) ? q : (z == 1) ? k : v;
    __nv_bfloat16* A2 = (z == 0) ? aq : (z == 1) ? ak : av;
    size_t i = (size_t)blockIdx.x * 256 + threadIdx.x;
    int row = (int)(i >> 10);
    int kk  = (int)(i & 1023);
    __nv_bfloat16 hi, lo;
    split1(A[i], hi, lo);
    size_t base = (size_t)row * GK;
    A2[base + kk]        = hi;
    A2[base + 1024 + kk] = lo;
    A2[base + 2048 + kk] = hi;
}

// batched weight transpose+split: z selects {Wq,Wk,Wv,Wo}
__global__ __launch_bounds__(256) void conv_w4(
    const float* __restrict__ Wq, const float* __restrict__ Wk,
    const float* __restrict__ Wv, const float* __restrict__ Wo,
    __nv_bfloat16* __restrict__ Tq, __nv_bfloat16* __restrict__ Tk,
    __nv_bfloat16* __restrict__ Tv, __nv_bfloat16* __restrict__ To)
{
    int z = blockIdx.z;
    const float* W = (z == 0) ? Wq : (z == 1) ? Wk : (z == 2) ? Wv : Wo;
    __nv_bfloat16* Wt = (z == 0) ? Tq : (z == 1) ? Tk : (z == 2) ? Tv : To;
    __shared__ float t[32][33];
    int tx = threadIdx.x, ty = threadIdx.y;
    int n0 = blockIdx.x * 32, k0 = blockIdx.y * 32;
#pragma unroll
    for (int i = 0; i < 4; i++)
        t[ty * 4 + i][tx] = W[(size_t)(k0 + ty * 4 + i) * Dm + n0 + tx];
    __syncthreads();
#pragma unroll
    for (int i = 0; i < 4; i++) {
        int n = ty * 4 + i;
        __nv_bfloat16 hi, lo;
        split1(t[tx][n], hi, lo);
        size_t base = (size_t)(n0 + n) * GK;
        Wt[base + k0 + tx]        = hi;
        Wt[base + 1024 + k0 + tx] = hi;
        Wt[base + 2048 + k0 + tx] = lo;
    }
}

__global__ __launch_bounds__(256) void conv_mask(
    const int* __restrict__ m, float* __restrict__ mf)
{
    int i = blockIdx.x * 256 + threadIdx.x;
    if (i < Bz * SKL) mf[i] = m[i] ? 1.0f : 0.0f;
}

// ============================================================================
// GEMM core: 128x128 tile, 3-stage cp.async pipeline, mma.sync bf16
// ============================================================================
#define SST   144
#define MATB  (128 * SST)
#define STAGEB (2 * MATB)          // 36864
#define GEMM_SMEM (3 * STAGEB)     // 110592

__device__ __forceinline__ void gemm_core(
    const char* gA, const char* gB, uint32_t sb, int tid,
    int warp_m, int warp_n, int lane, float acc[4][4][4])
{
    int lrow[4], lcol[4];
#pragma unroll
    for (int it = 0; it < 4; it++) {
        int f = tid + it * 256;
        lrow[it] = f >> 3;
        lcol[it] = (f & 7) * 16;
    }
#pragma unroll
    for (int mt = 0; mt < 4; mt++)
#pragma unroll
        for (int nt = 0; nt < 4; nt++)
#pragma unroll
            for (int r = 0; r < 4; r++) acc[mt][nt][r] = 0.f;

    // prologue: prefetch chunks 0, 1
#pragma unroll
    for (int p = 0; p < 2; p++) {
        uint32_t as = sb + p * STAGEB, bs = as + MATB;
#pragma unroll
        for (int it = 0; it < 4; it++) {
            long go = (long)lrow[it] * (GK * 2) + p * 128 + lcol[it];
            uint32_t so = (uint32_t)(lrow[it] * SST + lcol[it]);
            CP_ASYNC16(as + so, gA + go);
            CP_ASYNC16(bs + so, gB + go);
        }
        CP_COMMIT();
    }

    for (int c = 0; c < NCHUNK; c++) {
        if (c + 2 < NCHUNK) {
            int stn = (c + 2) % 3;
            uint32_t as = sb + stn * STAGEB, bs = as + MATB;
#pragma unroll
            for (int it = 0; it < 4; it++) {
                long go = (long)lrow[it] * (GK * 2) + (c + 2) * 128 + lcol[it];
                uint32_t so = (uint32_t)(lrow[it] * SST + lcol[it]);
                CP_ASYNC16(as + so, gA + go);
                CP_ASYNC16(bs + so, gB + go);
            }
            CP_COMMIT();
            CP_WAIT2();
        } else {
            CP_WAIT0();
        }
        __syncthreads();

        uint32_t aS = sb + (c % 3) * STAGEB;
        uint32_t bS = aS + MATB;

        int arow = warp_m * 64 + (lane & 15);
        int acol = ((lane >> 4) << 3);
        int brow = warp_n * 32 + (lane & 7) + ((lane >> 4) << 3);
        int bcol = (((lane >> 3) & 1) << 3);

#pragma unroll
        for (int ks = 0; ks < 4; ks++) {
            uint32_t a[4][4];
            uint32_t b[4][2];
#pragma unroll
            for (int mt = 0; mt < 4; mt++) {
                uint32_t ad = aS + (uint32_t)((arow + mt * 16) * SST
                                              + (ks * 16 + acol) * 2);
                LDMX4(a[mt][0], a[mt][1], a[mt][2], a[mt][3], ad);
            }
#pragma unroll
            for (int nh = 0; nh < 2; nh++) {
                uint32_t bd = bS + (uint32_t)((brow + nh * 16) * SST
                                              + (ks * 16 + bcol) * 2);
                LDMX4(b[nh * 2][0], b[nh * 2][1],
                      b[nh * 2 + 1][0], b[nh * 2 + 1][1], bd);
            }
#pragma unroll
            for (int mt = 0; mt < 4; mt++)
#pragma unroll
                for (int nt = 0; nt < 4; nt++)
                    MMA16816(acc[mt][nt], a[mt], b[nt]);
        }
        __syncthreads();
    }
}

// Batched QKV projection GEMM. z=0: qp fp32 + q2[hi,lo,hi]; z=1: k2[hi,hi,lo];
// z=2: v2 bf16.
__global__ __launch_bounds__(256) void gemm_qkv(
    const __nv_bfloat16* __restrict__ aq, const __nv_bfloat16* __restrict__ ak,
    const __nv_bfloat16* __restrict__ av,
    const __nv_bfloat16* __restrict__ wq, const __nv_bfloat16* __restrict__ wk,
    const __nv_bfloat16* __restrict__ wv,
    const float* __restrict__ bq, const float* __restrict__ bk,
    const float* __restrict__ bv,
    float* __restrict__ qp, __nv_bfloat16* __restrict__ q2,
    __nv_bfloat16* __restrict__ k2, __nv_bfloat16* __restrict__ v2)
{
    extern __shared__ char smem[];
    uint32_t sb = smem_u32(smem);
    int tid  = threadIdx.x;
    int wid  = tid >> 5;
    int lane = tid & 31;
    int bx = blockIdx.x, by = blockIdx.y, z = blockIdx.z;
    int warp_m = wid >> 2, warp_n = wid & 3;

    const __nv_bfloat16* A2 = (z == 0) ? aq : (z == 1) ? ak : av;
    const __nv_bfloat16* B2 = (z == 0) ? wq : (z == 1) ? wk : wv;
    const float* bias       = (z == 0) ? bq : (z == 1) ? bk : bv;

    float acc[4][4][4];
    gemm_core((const char*)(A2 + (size_t)(by * 128) * GK),
              (const char*)(B2 + (size_t)(bx * 128) * GK),
              sb, tid, warp_m, warp_n, lane, acc);

    int g  = lane >> 2;
    int tg = lane & 3;
#pragma unroll
    for (int mt = 0; mt < 4; mt++) {
        int row0 = by * 128 + warp_m * 64 + mt * 16 + g;
#pragma unroll
        for (int nt = 0; nt < 4; nt++) {
            int col = bx * 128 + warp_n * 32 + nt * 8 + tg * 2;
            float2 bv2 = *(const float2*)(bias + col);
            int h = col >> 6, d = col & 63;
#pragma unroll
            for (int half = 0; half < 2; half++) {
                int row = row0 + half * 8;
                float v0 = acc[mt][nt][2 * half]     + bv2.x;
                float v1 = acc[mt][nt][2 * half + 1] + bv2.y;
                int bb = row >> 11, r = row & 2047;
                size_t hb = (size_t)((bb * 16 + h) * 2048 + r);
                __nv_bfloat16 h0, l0, h1, l1;
                split1(v0, h0, l0);
                split1(v1, h1, l1);
                uint32_t hp = *(uint32_t*)&h0 | ((uint32_t)*(uint16_t*)&h1 << 16);
                uint32_t lp = *(uint32_t*)&l0 | ((uint32_t)*(uint16_t*)&l1 << 16);
                // note: reinterpret 16-bit halves safely:
                uint16_t h0b = *(uint16_t*)&h0, h1b = *(uint16_t*)&h1;
                uint16_t l0b = *(uint16_t*)&l0, l1b = *(uint16_t*)&l1;
                hp = (uint32_t)h0b | ((uint32_t)h1b << 16);
                lp = (uint32_t)l0b | ((uint32_t)l1b << 16);
                if (z == 0) {
                    float2 o = {v0, v1};
                    *(float2*)(qp + (size_t)row * Dm + col) = o;
                    size_t base = hb * HD2;
                    *(uint32_t*)(q2 + base + d)       = hp;
                    *(uint32_t*)(q2 + base + 64 + d)  = lp;
                    *(uint32_t*)(q2 + base + 128 + d) = hp;
                } else if (z == 1) {
                    size_t base = hb * HD2;
                    *(uint32_t*)(k2 + base + d)       = hp;
                    *(uint32_t*)(k2 + base + 64 + d)  = hp;
                    *(uint32_t*)(k2 + base + 128 + d) = lp;
                } else {
                    *(uint32_t*)(v2 + hb * DHd + d) = hp;
                }
            }
        }
    }
}

// Output projection GEMM: plain fp32 epilogue
__global__ __launch_bounds__(256) void gemm_o(
    const __nv_bfloat16* __restrict__ A2, const __nv_bfloat16* __restrict__ B2,
    const float* __restrict__ bias, float* __restrict__ C)
{
    extern __shared__ char smem[];
    uint32_t sb = smem_u32(smem);
    int tid  = threadIdx.x;
    int wid  = tid >> 5;
    int lane = tid & 31;
    int bx = blockIdx.x, by = blockIdx.y;
    int warp_m = wid >> 2, warp_n = wid & 3;

    float acc[4][4][4];
    gemm_core((const char*)(A2 + (size_t)(by * 128) * GK),
              (const char*)(B2 + (size_t)(bx * 128) * GK),
              sb, tid, warp_m, warp_n, lane, acc);

    int g  = lane >> 2;
    int tg = lane & 3;
#pragma unroll
    for (int mt = 0; mt < 4; mt++) {
        int row = by * 128 + warp_m * 64 + mt * 16 + g;
#pragma unroll
        for (int nt = 0; nt < 4; nt++) {
            int col = bx * 128 + warp_n * 32 + nt * 8 + tg * 2;
            float2 bv = *(const float2*)(bias + col);
            float2 o0 = {acc[mt][nt][0] + bv.x, acc[mt][nt][1] + bv.y};
            float2 o1 = {acc[mt][nt][2] + bv.x, acc[mt][nt][3] + bv.y};
            *(float2*)(C + (size_t)row * Dm + col)       = o0;
            *(float2*)(C + (size_t)(row + 8) * Dm + col) = o1;
        }
    }
}

// ============================================================================
// Flash attention, mma.sync bf16 (unchanged from R9)
// ============================================================================
#define QROWB 400
#define VROWB 144
#define KTILEB (64 * QROWB)
#define VOFF   KTILEB
#define MOFF   (KTILEB + 64 * VROWB)
#define STGB   (MOFF + 256)
#define FLASH_SMEM (2 * STGB)

__global__ __launch_bounds__(256, 1) void flash_mma(
    const __nv_bfloat16* __restrict__ Q2, const __nv_bfloat16* __restrict__ K2,
    const __nv_bfloat16* __restrict__ V2, const float* __restrict__ MF,
    float* __restrict__ attn)
{
    extern __shared__ char smem[];
    uint32_t sb = smem_u32(smem);
    int tid  = threadIdx.x;
    int wid  = tid >> 5;
    int lane = tid & 31;
    int qx = blockIdx.x, h = blockIdx.y, b = blockIdx.z;

    size_t bh = (size_t)(b * 16 + h) * 2048;
    const char* gQ = (const char*)(Q2 + (bh + qx * 128) * HD2);
    const char* gK = (const char*)(K2 + bh * HD2);
    const char* gV = (const char*)(V2 + bh * DHd);
    const char* gM = (const char*)(MF + b * SKL);

#pragma unroll
    for (int it = 0; it < 12; it++) {
        int f = tid + it * 256;
        int r = f / 24, c = f % 24;
        CP_ASYNC16(sb + r * QROWB + c * 16, gQ + (long)r * (HD2 * 2) + c * 16);
    }
    CP_COMMIT();
    CP_WAIT0();
    __syncthreads();

    uint32_t qf[12][4];
    {
        int arow = wid * 16 + (lane & 15);
        int acol = ((lane >> 4) << 3);
#pragma unroll
        for (int ks = 0; ks < 12; ks++)
            LDMX4(qf[ks][0], qf[ks][1], qf[ks][2], qf[ks][3],
                  sb + arow * QROWB + (ks * 16 + acol) * 2);
    }
    __syncthreads();

    int g  = lane >> 2;
    int tg = lane & 3;

    float O[8][4];
#pragma unroll
    for (int dt = 0; dt < 8; dt++)
#pragma unroll
        for (int r = 0; r < 4; r++) O[dt][r] = 0.f;
    float m0 = -30000.f, m1 = -30000.f, l0 = 0.f, l1 = 0.f;

    const float scale = 0.03125f;

#pragma unroll
    for (int it = 0; it < 6; it++) {
        int f = tid + it * 256;
        int r = f / 24, c = f % 24;
        CP_ASYNC16(sb + r * QROWB + c * 16, gK + (long)r * (HD2 * 2) + c * 16);
    }
#pragma unroll
    for (int it = 0; it < 2; it++) {
        int f = tid + it * 256;
        int r = f >> 3, c = f & 7;
        CP_ASYNC16(sb + VOFF + r * VROWB + c * 16, gV + (long)r * 128 + c * 16);
    }
    if (tid < 16) CP_ASYNC16(sb + MOFF + tid * 16, gM + tid * 16);
    CP_COMMIT();

    for (int kt = 0; kt < 32; kt++) {
        int st = kt & 1;
        if (kt + 1 < 32) {
            uint32_t ds = sb + (st ^ 1) * STGB;
            const char* nK = gK + (long)(kt + 1) * 64 * (HD2 * 2);
            const char* nV = gV + (long)(kt + 1) * 64 * 128;
#pragma unroll
            for (int it = 0; it < 6; it++) {
                int f = tid + it * 256;
                int r = f / 24, c = f % 24;
                CP_ASYNC16(ds + r * QROWB + c * 16, nK + (long)r * (HD2 * 2) + c * 16);
            }
#pragma unroll
            for (int it = 0; it < 2; it++) {
                int f = tid + it * 256;
                int r = f >> 3, c = f & 7;
                CP_ASYNC16(ds + VOFF + r * VROWB + c * 16, nV + (long)r * 128 + c * 16);
            }
            if (tid < 16)
                CP_ASYNC16(ds + MOFF + tid * 16, gM + (kt + 1) * 256 + tid * 16);
            CP_COMMIT();
            CP_WAIT1();
        } else {
            CP_WAIT0();
        }
        __syncthreads();

        uint32_t kS = sb + st * STGB;
        uint32_t vS = kS + VOFF;
        uint32_t mS = kS + MOFF;

        float s[8][4];
#pragma unroll
        for (int nt = 0; nt < 8; nt++)
#pragma unroll
            for (int r = 0; r < 4; r++) s[nt][r] = 0.f;

        int brow = (lane & 7) + ((lane >> 4) << 3);
        int bcol = (((lane >> 3) & 1) << 3);
#pragma unroll
        for (int ks = 0; ks < 12; ks++) {
#pragma unroll
            for (int j = 0; j < 4; j++) {
                uint32_t bfr[2][2];
                LDMX4(bfr[0][0], bfr[0][1], bfr[1][0], bfr[1][1],
                      kS + (j * 16 + brow) * QROWB + (ks * 16 + bcol) * 2);
                MMA16816(s[2 * j],     qf[ks], bfr[0]);
                MMA16816(s[2 * j + 1], qf[ks], bfr[1]);
            }
        }

        float mf[8][2];
#pragma unroll
        for (int nt = 0; nt < 8; nt++) {
            mf[nt][0] = *(const float*)((const char*)smem + (mS - sb) + (nt * 8 + 2 * tg) * 4);
            mf[nt][1] = *(const float*)((const char*)smem + (mS - sb) + (nt * 8 + 2 * tg + 1) * 4);
        }
        float rm0 = -30000.f, rm1 = -30000.f;
#pragma unroll
        for (int nt = 0; nt < 8; nt++) {
#pragma unroll
            for (int e = 0; e < 2; e++) {
                float off = (mf[nt][e] - 1.0f) * 30000.f;
                s[nt][e]     = s[nt][e]     * scale + off;
                s[nt][2 + e] = s[nt][2 + e] * scale + off;
                rm0 = fmaxf(rm0, s[nt][e]);
                rm1 = fmaxf(rm1, s[nt][2 + e]);
            }
        }
        rm0 = fmaxf(rm0, __shfl_xor_sync(0xffffffffu, rm0, 1));
        rm0 = fmaxf(rm0, __shfl_xor_sync(0xffffffffu, rm0, 2));
        rm1 = fmaxf(rm1, __shfl_xor_sync(0xffffffffu, rm1, 1));
        rm1 = fmaxf(rm1, __shfl_xor_sync(0xffffffffu, rm1, 2));

        float mn0 = fmaxf(m0, rm0), mn1 = fmaxf(m1, rm1);
        float al0 = __expf(m0 - mn0), al1 = __expf(m1 - mn1);
        m0 = mn0; m1 = mn1;

        float rs0 = 0.f, rs1 = 0.f;
#pragma unroll
        for (int nt = 0; nt < 8; nt++) {
#pragma unroll
            for (int e = 0; e < 2; e++) {
                float p0 = __expf(s[nt][e]     - mn0) * mf[nt][e];
                float p1 = __expf(s[nt][2 + e] - mn1) * mf[nt][e];
                s[nt][e] = p0;  s[nt][2 + e] = p1;
                rs0 += p0;  rs1 += p1;
            }
        }
        rs0 += __shfl_xor_sync(0xffffffffu, rs0, 1);
        rs0 += __shfl_xor_sync(0xffffffffu, rs0, 2);
        rs1 += __shfl_xor_sync(0xffffffffu, rs1, 1);
        rs1 += __shfl_xor_sync(0xffffffffu, rs1, 2);
        l0 = l0 * al0 + rs0;
        l1 = l1 * al1 + rs1;

#pragma unroll
        for (int dt = 0; dt < 8; dt++) {
            O[dt][0] *= al0; O[dt][1] *= al0;
            O[dt][2] *= al1; O[dt][3] *= al1;
        }

        int vrow = (lane & 7) + (((lane >> 3) & 1) << 3);
        int vcol = ((lane >> 4) << 3);
#pragma unroll
        for (int ks = 0; ks < 4; ks++) {
            uint32_t pa[4];
            pa[0] = packbf(s[2 * ks][0],     s[2 * ks][1]);
            pa[1] = packbf(s[2 * ks][2],     s[2 * ks][3]);
            pa[2] = packbf(s[2 * ks + 1][0], s[2 * ks + 1][1]);
            pa[3] = packbf(s[2 * ks + 1][2], s[2 * ks + 1][3]);
#pragma unroll
            for (int j = 0; j < 4; j++) {
                uint32_t bfr[2][2];
                LDMX4T(bfr[0][0], bfr[0][1], bfr[1][0], bfr[1][1],
                       vS + (ks * 16 + vrow) * VROWB + (j * 16 + vcol) * 2);
                MMA16816(O[2 * j],     pa, bfr[0]);
                MMA16816(O[2 * j + 1], pa, bfr[1]);
            }
        }
        __syncthreads();
    }

    float inv0 = l0 > 0.f ? 1.f / l0 : 0.f;
    float inv1 = l1 > 0.f ? 1.f / l1 : 0.f;
    int row0 = qx * 128 + wid * 16 + g;
    float* oBase = attn + (size_t)(b * SQL) * Dm + h * DHd;
#pragma unroll
    for (int dt = 0; dt < 8; dt++) {
        int col = dt * 8 + 2 * tg;
        float2 o0 = {O[dt][0] * inv0, O[dt][1] * inv0};
        float2 o1 = {O[dt][2] * inv1, O[dt][3] * inv1};
        *(float2*)(oBase + (size_t)row0 * Dm + col)       = o0;
        *(float2*)(oBase + (size_t)(row0 + 8) * Dm + col) = o1;
    }
}

// ============================================================================
// out = LayerNorm(X + (relu? relu(Y) : Y)) * g + beta; optional split output
// ============================================================================
__global__ __launch_bounds__(256) void add_ln(
    const float* __restrict__ X, const float* __restrict__ Y,
    const float* __restrict__ g, const float* __restrict__ be,
    float* __restrict__ out, __nv_bfloat16* __restrict__ a2, int dorelu)
{
    int row = blockIdx.x;
    int tid = threadIdx.x;
    size_t base = (size_t)row * Dm + tid * 4;

    float4 x4 = *(const float4*)(X + base);
    float4 y4 = *(const float4*)(Y + base);
    if (dorelu) {
        y4.x = fmaxf(y4.x, 0.f); y4.y = fmaxf(y4.y, 0.f);
        y4.z = fmaxf(y4.z, 0.f); y4.w = fmaxf(y4.w, 0.f);
    }
    float v[4] = {x4.x + y4.x, x4.y + y4.y, x4.z + y4.z, x4.w + y4.w};

    float s  = v[0] + v[1] + v[2] + v[3];
    float sq = v[0]*v[0] + v[1]*v[1] + v[2]*v[2] + v[3]*v[3];
#pragma unroll
    for (int off = 16; off > 0; off >>= 1) {
        s  += __shfl_xor_sync(0xffffffffu, s,  off);
        sq += __shfl_xor_sync(0xffffffffu, sq, off);
    }
    __shared__ float sh[16];
    int w = tid >> 5;
    if ((tid & 31) == 0) { sh[w] = s; sh[8 + w] = sq; }
    __syncthreads();
    s = 0.f; sq = 0.f;
#pragma unroll
    for (int i = 0; i < 8; i++) { s += sh[i]; sq += sh[8 + i]; }

    float mean = s * (1.f / 1024.f);
    float var  = fmaf(-mean, mean, sq * (1.f / 1024.f));
    float rstd = rsqrtf(var + 1e-6f);

    float4 g4 = *(const float4*)(g  + tid * 4);
    float4 b4 = *(const float4*)(be + tid * 4);
    float o[4];
    o[0] = (v[0] - mean) * rstd * g4.x + b4.x;
    o[1] = (v[1] - mean) * rstd * g4.y + b4.y;
    o[2] = (v[2] - mean) * rstd * g4.z + b4.z;
    o[3] = (v[3] - mean) * rstd * g4.w + b4.w;
    *(float4*)(out + base) = *(float4*)o;

    if (a2) {
        size_t ab = (size_t)row * GK + tid * 4;
        uint32_t hp[2], lp[2];
#pragma unroll
        for (int i = 0; i < 2; i++) {
            __nv_bfloat16 h0, l0, h1, l1;
            split1(o[2 * i], h0, l0);
            split1(o[2 * i + 1], h1, l1);
            hp[i] = (uint32_t)(*(uint16_t*)&h0) | ((uint32_t)(*(uint16_t*)&h1) << 16);
            lp[i] = (uint32_t)(*(uint16_t*)&l0) | ((uint32_t)(*(uint16_t*)&l1) << 16);
        }
        *(uint2*)(a2 + ab)        = make_uint2(hp[0], hp[1]);
        *(uint2*)(a2 + ab + 1024) = make_uint2(lp[0], lp[1]);
        *(uint2*)(a2 + ab + 2048) = make_uint2(hp[0], hp[1]);
    }
}

// ============================================================================
extern "C" void kernel_launch(void* const* d_in, const int* in_sizes, int n_in,
                              void* d_out, int out_size)
{
    const float* q    = (const float*)d_in[0];
    const float* k    = (const float*)d_in[1];
    const float* v    = (const float*)d_in[2];
    const int*   mask = (const int*)d_in[3];
    const float* Wq   = (const float*)d_in[4];
    const float* bq   = (const float*)d_in[5];
    const float* Wk   = (const float*)d_in[6];
    const float* bk   = (const float*)d_in[7];
    const float* Wv   = (const float*)d_in[8];
    const float* bv   = (const float*)d_in[9];
    const float* Wo   = (const float*)d_in[10];
    const float* bo   = (const float*)d_in[11];
    const float* g1   = (const float*)d_in[12];
    const float* b1   = (const float*)d_in[13];
    const float* g2   = (const float*)d_in[14];
    const float* b2   = (const float*)d_in[15];

    float *qp, *at, *x, *y, *mf;
    __nv_bfloat16 *aq, *ak, *av, *w2q, *w2k, *w2v, *w2o, *q2, *k2, *v2;
    cudaGetSymbolAddress((void**)&qp, g_qp);
    cudaGetSymbolAddress((void**)&at, g_att);
    cudaGetSymbolAddress((void**)&x,  g_x);
    cudaGetSymbolAddress((void**)&y,  g_y);
    cudaGetSymbolAddress((void**)&aq,  g_a2q);
    cudaGetSymbolAddress((void**)&ak,  g_a2k);
    cudaGetSymbolAddress((void**)&av,  g_a2v);
    cudaGetSymbolAddress((void**)&w2q, g_w2q);
    cudaGetSymbolAddress((void**)&w2k, g_w2k);
    cudaGetSymbolAddress((void**)&w2v, g_w2v);
    cudaGetSymbolAddress((void**)&w2o, g_w2o);
    cudaGetSymbolAddress((void**)&q2,  g_q2x);
    cudaGetSymbolAddress((void**)&k2,  g_k2x);
    cudaGetSymbolAddress((void**)&v2,  g_v2x);
    cudaGetSymbolAddress((void**)&mf,  g_mf);

    cudaFuncSetAttribute(gemm_qkv, cudaFuncAttributeMaxDynamicSharedMemorySize,
                         GEMM_SMEM);
    cudaFuncSetAttribute(gemm_o, cudaFuncAttributeMaxDynamicSharedMemorySize,
                         GEMM_SMEM);
    cudaFuncSetAttribute(flash_mma, cudaFuncAttributeMaxDynamicSharedMemorySize,
                         FLASH_SMEM);

    conv_w4<<<dim3(Dm / 32, Dm / 32, 4), dim3(32, 8)>>>(
        Wq, Wk, Wv, Wo, w2q, w2k, w2v, w2o);

    int cab = (int)(((size_t)NR * Dm) / 256);
    conv_a3<<<dim3(cab, 1, 3), 256>>>(q, k, v, aq, ak, av);
    conv_mask<<<(Bz * SKL + 255) / 256, 256>>>(mask, mf);

    gemm_qkv<<<dim3(Dm / 128, NR / 128, 3), 256, GEMM_SMEM>>>(
        aq, ak, av, w2q, w2k, w2v, bq, bk, bv, qp, q2, k2, v2);

    flash_mma<<<dim3(SQL / 128, Hh, Bz), 256, FLASH_SMEM>>>(q2, k2, v2, mf, at);

    add_ln<<<NR, 256>>>(qp, at, g1, b1, x, aq, 0);

    gemm_o<<<dim3(Dm / 128, NR / 128), 256, GEMM_SMEM>>>(aq, w2o, bo, y);

    add_ln<<<NR, 256>>>(x, y, g2, b2, (float*)d_out, (/*a2*/ (__nv_bfloat16*)0), 1);
}

// round 11
// speedup vs baseline: 3.5188x; 1.0349x over previous
#include <cuda_runtime.h>
#include <cuda_bf16.h>
#include <cstdint>
#include <math.h>

// Problem constants
#define Bz   4
#define SQL  2048
#define SKL  2048
#define Dm   1024
#define Hh   16
#define DHd  64
#define NR   (Bz*SQL)          // 8192 rows
#define GK   3072              // split-bf16 K' = 3*1024
#define NCHUNK 48              // GK / 64
#define HD2  192               // split head dim 3*64

// -------- scratch (device globals; no allocation allowed) --------
__device__ float g_qp [NR*Dm];
__device__ float g_att[NR*Dm];
__device__ float g_x  [NR*Dm];
__device__ float g_y  [NR*Dm];
__device__ __nv_bfloat16 g_a2q[(size_t)NR*GK];
__device__ __nv_bfloat16 g_a2k[(size_t)NR*GK];
__device__ __nv_bfloat16 g_a2v[(size_t)NR*GK];
__device__ __nv_bfloat16 g_w2q[(size_t)Dm*GK];
__device__ __nv_bfloat16 g_w2k[(size_t)Dm*GK];
__device__ __nv_bfloat16 g_w2v[(size_t)Dm*GK];
__device__ __nv_bfloat16 g_w2o[(size_t)Dm*GK];
__device__ __nv_bfloat16 g_q2x[(size_t)Bz*Hh*SQL*HD2];
__device__ __nv_bfloat16 g_k2x[(size_t)Bz*Hh*SKL*HD2];
__device__ __nv_bfloat16 g_v2x[(size_t)Bz*Hh*SKL*DHd];
__device__ float g_mf [Bz*SKL];

// ============================================================================
// helpers
// ============================================================================
__device__ __forceinline__ uint32_t smem_u32(const void* p) {
    uint32_t a;
    asm("{ .reg .u64 t; cvta.to.shared.u64 t, %1; cvt.u32.u64 %0, t; }"
        : "=r"(a) : "l"(p));
    return a;
}
#define CP_ASYNC16(saddr, gptr) \
    asm volatile("cp.async.cg.shared.global [%0], [%1], 16;" \
                 :: "r"(saddr), "l"(gptr))
#define CP_COMMIT() asm volatile("cp.async.commit_group;" ::: "memory")
#define CP_WAIT1()  asm volatile("cp.async.wait_group 1;" ::: "memory")
#define CP_WAIT0()  asm volatile("cp.async.wait_group 0;" ::: "memory")

#define LDMX4(r0,r1,r2,r3,addr) \
    asm volatile("ldmatrix.sync.aligned.m8n8.x4.shared.b16 {%0,%1,%2,%3}, [%4];" \
                 : "=r"(r0), "=r"(r1), "=r"(r2), "=r"(r3) : "r"(addr))
#define LDMX4T(r0,r1,r2,r3,addr) \
    asm volatile("ldmatrix.sync.aligned.m8n8.x4.trans.shared.b16 {%0,%1,%2,%3}, [%4];" \
                 : "=r"(r0), "=r"(r1), "=r"(r2), "=r"(r3) : "r"(addr))

#define MMA16816(d, a, b) \
    asm volatile("mma.sync.aligned.m16n8k16.row.col.f32.bf16.bf16.f32 " \
                 "{%0,%1,%2,%3}, {%4,%5,%6,%7}, {%8,%9}, {%0,%1,%2,%3};" \
                 : "+f"((d)[0]), "+f"((d)[1]), "+f"((d)[2]), "+f"((d)[3]) \
                 : "r"((a)[0]), "r"((a)[1]), "r"((a)[2]), "r"((a)[3]), \
                   "r"((b)[0]), "r"((b)[1]))

__device__ __forceinline__ uint32_t packbf(float a, float b) {
    __nv_bfloat162 t = __floats2bfloat162_rn(a, b);
    return *(uint32_t*)&t;
}
__device__ __forceinline__ void split1(float v, __nv_bfloat16& hi, __nv_bfloat16& lo) {
    hi = __float2bfloat16(v);
    lo = __float2bfloat16(v - __bfloat162float(hi));
}
__device__ __forceinline__ uint32_t pack2(__nv_bfloat16 a, __nv_bfloat16 b) {
    return (uint32_t)(*(uint16_t*)&a) | ((uint32_t)(*(uint16_t*)&b) << 16);
}

// ============================================================================
// conversion kernels
// ============================================================================
// batched: z=0 q, z=1 k, z=2 v  -> a2 split [hi, lo, hi]; float4 vectorized
__global__ __launch_bounds__(256) void conv_a3(
    const float* __restrict__ q, const float* __restrict__ k,
    const float* __restrict__ v,
    __nv_bfloat16* __restrict__ aq, __nv_bfloat16* __restrict__ ak,
    __nv_bfloat16* __restrict__ av)
{
    int z = blockIdx.z;
    const float* A = (z == 0) ? q : (z == 1) ? k : v;
    __nv_bfloat16* A2 = (z == 0) ? aq : (z == 1) ? ak : av;
    size_t i4 = (size_t)blockIdx.x * 256 + threadIdx.x;   // vec4 index
    size_t e  = i4 * 4;
    int row = (int)(e >> 10);
    int kk  = (int)(e & 1023);
    float4 vv = *(const float4*)(A + e);
    __nv_bfloat16 h0, l0, h1, l1, h2, l2, h3, l3;
    split1(vv.x, h0, l0); split1(vv.y, h1, l1);
    split1(vv.z, h2, l2); split1(vv.w, h3, l3);
    uint2 hp = make_uint2(pack2(h0, h1), pack2(h2, h3));
    uint2 lp = make_uint2(pack2(l0, l1), pack2(l2, l3));
    size_t base = (size_t)row * GK + kk;
    *(uint2*)(A2 + base)        = hp;
    *(uint2*)(A2 + base + 1024) = lp;
    *(uint2*)(A2 + base + 2048) = hp;
}

// batched weight transpose+split: z selects {Wq,Wk,Wv,Wo}
__global__ __launch_bounds__(256) void conv_w4(
    const float* __restrict__ Wq, const float* __restrict__ Wk,
    const float* __restrict__ Wv, const float* __restrict__ Wo,
    __nv_bfloat16* __restrict__ Tq, __nv_bfloat16* __restrict__ Tk,
    __nv_bfloat16* __restrict__ Tv, __nv_bfloat16* __restrict__ To)
{
    int z = blockIdx.z;
    const float* W = (z == 0) ? Wq : (z == 1) ? Wk : (z == 2) ? Wv : Wo;
    __nv_bfloat16* Wt = (z == 0) ? Tq : (z == 1) ? Tk : (z == 2) ? Tv : To;
    __shared__ float t[32][33];
    int tx = threadIdx.x, ty = threadIdx.y;
    int n0 = blockIdx.x * 32, k0 = blockIdx.y * 32;
#pragma unroll
    for (int i = 0; i < 4; i++)
        t[ty * 4 + i][tx] = W[(size_t)(k0 + ty * 4 + i) * Dm + n0 + tx];
    __syncthreads();
#pragma unroll
    for (int i = 0; i < 4; i++) {
        int n = ty * 4 + i;
        __nv_bfloat16 hi, lo;
        split1(t[tx][n], hi, lo);
        size_t base = (size_t)(n0 + n) * GK;
        Wt[base + k0 + tx]        = hi;
        Wt[base + 1024 + k0 + tx] = hi;
        Wt[base + 2048 + k0 + tx] = lo;
    }
}

__global__ __launch_bounds__(256) void conv_mask(
    const int* __restrict__ m, float* __restrict__ mf)
{
    int i = blockIdx.x * 256 + threadIdx.x;
    if (i < Bz * SKL) mf[i] = m[i] ? 1.0f : 0.0f;
}

// ============================================================================
// GEMM core: 128x128 tile, 3-stage cp.async pipeline, ONE sync per chunk
// ============================================================================
#define SST   144
#define MATB  (128 * SST)
#define STAGEB (2 * MATB)          // 36864
#define GEMM_SMEM (3 * STAGEB)     // 110592

__device__ __forceinline__ void gemm_core(
    const char* gA, const char* gB, uint32_t sb, int tid,
    int warp_m, int warp_n, int lane, float acc[4][4][4])
{
    int lrow[4], lcol[4];
#pragma unroll
    for (int it = 0; it < 4; it++) {
        int f = tid + it * 256;
        lrow[it] = f >> 3;
        lcol[it] = (f & 7) * 16;
    }
#pragma unroll
    for (int mt = 0; mt < 4; mt++)
#pragma unroll
        for (int nt = 0; nt < 4; nt++)
#pragma unroll
            for (int r = 0; r < 4; r++) acc[mt][nt][r] = 0.f;

    // prologue: prefetch chunks 0, 1 into stages 0, 1
#pragma unroll
    for (int p = 0; p < 2; p++) {
        uint32_t as = sb + p * STAGEB, bs = as + MATB;
#pragma unroll
        for (int it = 0; it < 4; it++) {
            long go = (long)lrow[it] * (GK * 2) + p * 128 + lcol[it];
            uint32_t so = (uint32_t)(lrow[it] * SST + lcol[it]);
            CP_ASYNC16(as + so, gA + go);
            CP_ASYNC16(bs + so, gB + go);
        }
        CP_COMMIT();
    }

    int arow = warp_m * 64 + (lane & 15);
    int acol = ((lane >> 4) << 3);
    int brow = warp_n * 32 + (lane & 7) + ((lane >> 4) << 3);
    int bcol = (((lane >> 3) & 1) << 3);

    for (int c = 0; c < NCHUNK; c++) {
        // wait for chunk c's group, then one barrier
        if (c < NCHUNK - 1) { CP_WAIT1(); } else { CP_WAIT0(); }
        __syncthreads();
        // prefetch chunk c+2 into the stage consumed at iteration c-1
        if (c + 2 < NCHUNK) {
            uint32_t as = sb + ((c + 2) % 3) * STAGEB, bs = as + MATB;
#pragma unroll
            for (int it = 0; it < 4; it++) {
                long go = (long)lrow[it] * (GK * 2) + (c + 2) * 128 + lcol[it];
                uint32_t so = (uint32_t)(lrow[it] * SST + lcol[it]);
                CP_ASYNC16(as + so, gA + go);
                CP_ASYNC16(bs + so, gB + go);
            }
            CP_COMMIT();
        }

        uint32_t aS = sb + (c % 3) * STAGEB;
        uint32_t bS = aS + MATB;

#pragma unroll
        for (int ks = 0; ks < 4; ks++) {
            uint32_t a[4][4];
            uint32_t b[4][2];
#pragma unroll
            for (int mt = 0; mt < 4; mt++) {
                uint32_t ad = aS + (uint32_t)((arow + mt * 16) * SST
                                              + (ks * 16 + acol) * 2);
                LDMX4(a[mt][0], a[mt][1], a[mt][2], a[mt][3], ad);
            }
#pragma unroll
            for (int nh = 0; nh < 2; nh++) {
                uint32_t bd = bS + (uint32_t)((brow + nh * 16) * SST
                                              + (ks * 16 + bcol) * 2);
                LDMX4(b[nh * 2][0], b[nh * 2][1],
                      b[nh * 2 + 1][0], b[nh * 2 + 1][1], bd);
            }
#pragma unroll
            for (int mt = 0; mt < 4; mt++)
#pragma unroll
                for (int nt = 0; nt < 4; nt++)
                    MMA16816(acc[mt][nt], a[mt], b[nt]);
        }
    }
}

// Batched QKV projection GEMM. z=0: qp fp32 + q2[hi,lo,hi]; z=1: k2[hi,hi,lo];
// z=2: v2 bf16.
__global__ __launch_bounds__(256) void gemm_qkv(
    const __nv_bfloat16* __restrict__ aq, const __nv_bfloat16* __restrict__ ak,
    const __nv_bfloat16* __restrict__ av,
    const __nv_bfloat16* __restrict__ wq, const __nv_bfloat16* __restrict__ wk,
    const __nv_bfloat16* __restrict__ wv,
    const float* __restrict__ bq, const float* __restrict__ bk,
    const float* __restrict__ bv,
    float* __restrict__ qp, __nv_bfloat16* __restrict__ q2,
    __nv_bfloat16* __restrict__ k2, __nv_bfloat16* __restrict__ v2)
{
    extern __shared__ char smem[];
    uint32_t sb = smem_u32(smem);
    int tid  = threadIdx.x;
    int wid  = tid >> 5;
    int lane = tid & 31;
    int bx = blockIdx.x, by = blockIdx.y, z = blockIdx.z;
    int warp_m = wid >> 2, warp_n = wid & 3;

    const __nv_bfloat16* A2 = (z == 0) ? aq : (z == 1) ? ak : av;
    const __nv_bfloat16* B2 = (z == 0) ? wq : (z == 1) ? wk : wv;
    const float* bias       = (z == 0) ? bq : (z == 1) ? bk : bv;

    float acc[4][4][4];
    gemm_core((const char*)(A2 + (size_t)(by * 128) * GK),
              (const char*)(B2 + (size_t)(bx * 128) * GK),
              sb, tid, warp_m, warp_n, lane, acc);

    int g  = lane >> 2;
    int tg = lane & 3;
#pragma unroll
    for (int mt = 0; mt < 4; mt++) {
        int row0 = by * 128 + warp_m * 64 + mt * 16 + g;
#pragma unroll
        for (int nt = 0; nt < 4; nt++) {
            int col = bx * 128 + warp_n * 32 + nt * 8 + tg * 2;
            float2 bv2 = *(const float2*)(bias + col);
            int h = col >> 6, d = col & 63;
#pragma unroll
            for (int half = 0; half < 2; half++) {
                int row = row0 + half * 8;
                float v0 = acc[mt][nt][2 * half]     + bv2.x;
                float v1 = acc[mt][nt][2 * half + 1] + bv2.y;
                int bb = row >> 11, r = row & 2047;
                size_t hb = (size_t)((bb * 16 + h) * 2048 + r);
                __nv_bfloat16 h0, l0, h1, l1;
                split1(v0, h0, l0);
                split1(v1, h1, l1);
                uint32_t hp = pack2(h0, h1);
                uint32_t lp = pack2(l0, l1);
                if (z == 0) {
                    float2 o = {v0, v1};
                    *(float2*)(qp + (size_t)row * Dm + col) = o;
                    size_t base = hb * HD2;
                    *(uint32_t*)(q2 + base + d)       = hp;
                    *(uint32_t*)(q2 + base + 64 + d)  = lp;
                    *(uint32_t*)(q2 + base + 128 + d) = hp;
                } else if (z == 1) {
                    size_t base = hb * HD2;
                    *(uint32_t*)(k2 + base + d)       = hp;
                    *(uint32_t*)(k2 + base + 64 + d)  = hp;
                    *(uint32_t*)(k2 + base + 128 + d) = lp;
                } else {
                    *(uint32_t*)(v2 + hb * DHd + d) = hp;
                }
            }
        }
    }
}

// Output projection GEMM: plain fp32 epilogue
__global__ __launch_bounds__(256) void gemm_o(
    const __nv_bfloat16* __restrict__ A2, const __nv_bfloat16* __restrict__ B2,
    const float* __restrict__ bias, float* __restrict__ C)
{
    extern __shared__ char smem[];
    uint32_t sb = smem_u32(smem);
    int tid  = threadIdx.x;
    int wid  = tid >> 5;
    int lane = tid & 31;
    int bx = blockIdx.x, by = blockIdx.y;
    int warp_m = wid >> 2, warp_n = wid & 3;

    float acc[4][4][4];
    gemm_core((const char*)(A2 + (size_t)(by * 128) * GK),
              (const char*)(B2 + (size_t)(bx * 128) * GK),
              sb, tid, warp_m, warp_n, lane, acc);

    int g  = lane >> 2;
    int tg = lane & 3;
#pragma unroll
    for (int mt = 0; mt < 4; mt++) {
        int row = by * 128 + warp_m * 64 + mt * 16 + g;
#pragma unroll
        for (int nt = 0; nt < 4; nt++) {
            int col = bx * 128 + warp_n * 32 + nt * 8 + tg * 2;
            float2 bv = *(const float2*)(bias + col);
            float2 o0 = {acc[mt][nt][0] + bv.x, acc[mt][nt][1] + bv.y};
            float2 o1 = {acc[mt][nt][2] + bv.x, acc[mt][nt][3] + bv.y};
            *(float2*)(C + (size_t)row * Dm + col)       = o0;
            *(float2*)(C + (size_t)(row + 8) * Dm + col) = o1;
        }
    }
}

// ============================================================================
// Flash attention, mma.sync bf16; 3-stage ring, ONE sync per ktile
// ============================================================================
#define QROWB 400
#define VROWB 144
#define KTILEB (64 * QROWB)
#define VOFF   KTILEB
#define MOFF   (KTILEB + 64 * VROWB)
#define STGB   (MOFF + 256)        // 35072
#define FLASH_SMEM (3 * STGB)      // 105216

__device__ __forceinline__ void flash_prefetch(
    uint32_t ds, const char* gK, const char* gV, const char* gM,
    int kt, int tid)
{
    const char* nK = gK + (long)kt * 64 * (HD2 * 2);
    const char* nV = gV + (long)kt * 64 * 128;
#pragma unroll
    for (int it = 0; it < 6; it++) {
        int f = tid + it * 256;
        int r = f / 24, c = f % 24;
        CP_ASYNC16(ds + r * QROWB + c * 16, nK + (long)r * (HD2 * 2) + c * 16);
    }
#pragma unroll
    for (int it = 0; it < 2; it++) {
        int f = tid + it * 256;
        int r = f >> 3, c = f & 7;
        CP_ASYNC16(ds + VOFF + r * VROWB + c * 16, nV + (long)r * 128 + c * 16);
    }
    if (tid < 16) CP_ASYNC16(ds + MOFF + tid * 16, gM + kt * 256 + tid * 16);
    CP_COMMIT();
}

__global__ __launch_bounds__(256, 1) void flash_mma(
    const __nv_bfloat16* __restrict__ Q2, const __nv_bfloat16* __restrict__ K2,
    const __nv_bfloat16* __restrict__ V2, const float* __restrict__ MF,
    float* __restrict__ attn)
{
    extern __shared__ char smem[];
    uint32_t sb = smem_u32(smem);
    int tid  = threadIdx.x;
    int wid  = tid >> 5;
    int lane = tid & 31;
    int qx = blockIdx.x, h = blockIdx.y, b = blockIdx.z;

    size_t bh = (size_t)(b * 16 + h) * 2048;
    const char* gQ = (const char*)(Q2 + (bh + qx * 128) * HD2);
    const char* gK = (const char*)(K2 + bh * HD2);
    const char* gV = (const char*)(V2 + bh * DHd);
    const char* gM = (const char*)(MF + b * SKL);

    // ---- stage Q' into smem, then ldmatrix into registers ----
#pragma unroll
    for (int it = 0; it < 12; it++) {
        int f = tid + it * 256;
        int r = f / 24, c = f % 24;
        CP_ASYNC16(sb + r * QROWB + c * 16, gQ + (long)r * (HD2 * 2) + c * 16);
    }
    CP_COMMIT();
    CP_WAIT0();
    __syncthreads();

    uint32_t qf[12][4];
    {
        int arow = wid * 16 + (lane & 15);
        int acol = ((lane >> 4) << 3);
#pragma unroll
        for (int ks = 0; ks < 12; ks++)
            LDMX4(qf[ks][0], qf[ks][1], qf[ks][2], qf[ks][3],
                  sb + arow * QROWB + (ks * 16 + acol) * 2);
    }
    __syncthreads();   // Q smem region now reusable as stage buffers

    int g  = lane >> 2;
    int tg = lane & 3;

    float O[8][4];
#pragma unroll
    for (int dt = 0; dt < 8; dt++)
#pragma unroll
        for (int r = 0; r < 4; r++) O[dt][r] = 0.f;
    float m0 = -30000.f, m1 = -30000.f, l0 = 0.f, l1 = 0.f;

    const float scale = 0.03125f;

    // prologue: prefetch ktiles 0, 1 into stages 0, 1
    flash_prefetch(sb,        gK, gV, gM, 0, tid);
    flash_prefetch(sb + STGB, gK, gV, gM, 1, tid);

    for (int kt = 0; kt < 32; kt++) {
        if (kt < 31) { CP_WAIT1(); } else { CP_WAIT0(); }
        __syncthreads();
        if (kt + 2 < 32)
            flash_prefetch(sb + ((kt + 2) % 3) * STGB, gK, gV, gM, kt + 2, tid);

        uint32_t kS = sb + (kt % 3) * STGB;
        uint32_t vS = kS + VOFF;
        uint32_t mS = kS + MOFF;

        // ---- S = Q' K'^T ----
        float s[8][4];
#pragma unroll
        for (int nt = 0; nt < 8; nt++)
#pragma unroll
            for (int r = 0; r < 4; r++) s[nt][r] = 0.f;

        int brow = (lane & 7) + ((lane >> 4) << 3);
        int bcol = (((lane >> 3) & 1) << 3);
#pragma unroll
        for (int ks = 0; ks < 12; ks++) {
#pragma unroll
            for (int j = 0; j < 4; j++) {
                uint32_t bfr[2][2];
                LDMX4(bfr[0][0], bfr[0][1], bfr[1][0], bfr[1][1],
                      kS + (j * 16 + brow) * QROWB + (ks * 16 + bcol) * 2);
                MMA16816(s[2 * j],     qf[ks], bfr[0]);
                MMA16816(s[2 * j + 1], qf[ks], bfr[1]);
            }
        }

        // ---- softmax (online) ----
        float mf[8][2];
#pragma unroll
        for (int nt = 0; nt < 8; nt++) {
            mf[nt][0] = *(const float*)((const char*)smem + (mS - sb) + (nt * 8 + 2 * tg) * 4);
            mf[nt][1] = *(const float*)((const char*)smem + (mS - sb) + (nt * 8 + 2 * tg + 1) * 4);
        }
        float rm0 = -30000.f, rm1 = -30000.f;
#pragma unroll
        for (int nt = 0; nt < 8; nt++) {
#pragma unroll
            for (int e = 0; e < 2; e++) {
                float off = (mf[nt][e] - 1.0f) * 30000.f;
                s[nt][e]     = s[nt][e]     * scale + off;
                s[nt][2 + e] = s[nt][2 + e] * scale + off;
                rm0 = fmaxf(rm0, s[nt][e]);
                rm1 = fmaxf(rm1, s[nt][2 + e]);
            }
        }
        rm0 = fmaxf(rm0, __shfl_xor_sync(0xffffffffu, rm0, 1));
        rm0 = fmaxf(rm0, __shfl_xor_sync(0xffffffffu, rm0, 2));
        rm1 = fmaxf(rm1, __shfl_xor_sync(0xffffffffu, rm1, 1));
        rm1 = fmaxf(rm1, __shfl_xor_sync(0xffffffffu, rm1, 2));

        float mn0 = fmaxf(m0, rm0), mn1 = fmaxf(m1, rm1);
        float al0 = __expf(m0 - mn0), al1 = __expf(m1 - mn1);
        m0 = mn0; m1 = mn1;

        float rs0 = 0.f, rs1 = 0.f;
#pragma unroll
        for (int nt = 0; nt < 8; nt++) {
#pragma unroll
            for (int e = 0; e < 2; e++) {
                float p0 = __expf(s[nt][e]     - mn0) * mf[nt][e];
                float p1 = __expf(s[nt][2 + e] - mn1) * mf[nt][e];
                s[nt][e] = p0;  s[nt][2 + e] = p1;
                rs0 += p0;  rs1 += p1;
            }
        }
        rs0 += __shfl_xor_sync(0xffffffffu, rs0, 1);
        rs0 += __shfl_xor_sync(0xffffffffu, rs0, 2);
        rs1 += __shfl_xor_sync(0xffffffffu, rs1, 1);
        rs1 += __shfl_xor_sync(0xffffffffu, rs1, 2);
        l0 = l0 * al0 + rs0;
        l1 = l1 * al1 + rs1;

#pragma unroll
        for (int dt = 0; dt < 8; dt++) {
            O[dt][0] *= al0; O[dt][1] *= al0;
            O[dt][2] *= al1; O[dt][3] *= al1;
        }

        // ---- O += P V ----
        int vrow = (lane & 7) + (((lane >> 3) & 1) << 3);
        int vcol = ((lane >> 4) << 3);
#pragma unroll
        for (int ks = 0; ks < 4; ks++) {
            uint32_t pa[4];
            pa[0] = packbf(s[2 * ks][0],     s[2 * ks][1]);
            pa[1] = packbf(s[2 * ks][2],     s[2 * ks][3]);
            pa[2] = packbf(s[2 * ks + 1][0], s[2 * ks + 1][1]);
            pa[3] = packbf(s[2 * ks + 1][2], s[2 * ks + 1][3]);
#pragma unroll
            for (int j = 0; j < 4; j++) {
                uint32_t bfr[2][2];
                LDMX4T(bfr[0][0], bfr[0][1], bfr[1][0], bfr[1][1],
                       vS + (ks * 16 + vrow) * VROWB + (j * 16 + vcol) * 2);
                MMA16816(O[2 * j],     pa, bfr[0]);
                MMA16816(O[2 * j + 1], pa, bfr[1]);
            }
        }
    }

    float inv0 = l0 > 0.f ? 1.f / l0 : 0.f;
    float inv1 = l1 > 0.f ? 1.f / l1 : 0.f;
    int row0 = qx * 128 + wid * 16 + g;
    float* oBase = attn + (size_t)(b * SQL) * Dm + h * DHd;
#pragma unroll
    for (int dt = 0; dt < 8; dt++) {
        int col = dt * 8 + 2 * tg;
        float2 o0 = {O[dt][0] * inv0, O[dt][1] * inv0};
        float2 o1 = {O[dt][2] * inv1, O[dt][3] * inv1};
        *(float2*)(oBase + (size_t)row0 * Dm + col)       = o0;
        *(float2*)(oBase + (size_t)(row0 + 8) * Dm + col) = o1;
    }
}

// ============================================================================
// out = LayerNorm(X + (relu? relu(Y) : Y)) * g + beta; optional split output
// ============================================================================
__global__ __launch_bounds__(256) void add_ln(
    const float* __restrict__ X, const float* __restrict__ Y,
    const float* __restrict__ g, const float* __restrict__ be,
    float* __restrict__ out, __nv_bfloat16* __restrict__ a2, int dorelu)
{
    int row = blockIdx.x;
    int tid = threadIdx.x;
    size_t base = (size_t)row * Dm + tid * 4;

    float4 x4 = *(const float4*)(X + base);
    float4 y4 = *(const float4*)(Y + base);
    if (dorelu) {
        y4.x = fmaxf(y4.x, 0.f); y4.y = fmaxf(y4.y, 0.f);
        y4.z = fmaxf(y4.z, 0.f); y4.w = fmaxf(y4.w, 0.f);
    }
    float v[4] = {x4.x + y4.x, x4.y + y4.y, x4.z + y4.z, x4.w + y4.w};

    float s  = v[0] + v[1] + v[2] + v[3];
    float sq = v[0]*v[0] + v[1]*v[1] + v[2]*v[2] + v[3]*v[3];
#pragma unroll
    for (int off = 16; off > 0; off >>= 1) {
        s  += __shfl_xor_sync(0xffffffffu, s,  off);
        sq += __shfl_xor_sync(0xffffffffu, sq, off);
    }
    __shared__ float sh[16];
    int w = tid >> 5;
    if ((tid & 31) == 0) { sh[w] = s; sh[8 + w] = sq; }
    __syncthreads();
    s = 0.f; sq = 0.f;
#pragma unroll
    for (int i = 0; i < 8; i++) { s += sh[i]; sq += sh[8 + i]; }

    float mean = s * (1.f / 1024.f);
    float var  = fmaf(-mean, mean, sq * (1.f / 1024.f));
    float rstd = rsqrtf(var + 1e-6f);

    float4 g4 = *(const float4*)(g  + tid * 4);
    float4 b4 = *(const float4*)(be + tid * 4);
    float o[4];
    o[0] = (v[0] - mean) * rstd * g4.x + b4.x;
    o[1] = (v[1] - mean) * rstd * g4.y + b4.y;
    o[2] = (v[2] - mean) * rstd * g4.z + b4.z;
    o[3] = (v[3] - mean) * rstd * g4.w + b4.w;
    *(float4*)(out + base) = *(float4*)o;

    if (a2) {
        size_t ab = (size_t)row * GK + tid * 4;
        __nv_bfloat16 h0, l0, h1, l1, h2, l2, h3, l3;
        split1(o[0], h0, l0); split1(o[1], h1, l1);
        split1(o[2], h2, l2); split1(o[3], h3, l3);
        uint2 hp = make_uint2(pack2(h0, h1), pack2(h2, h3));
        uint2 lp = make_uint2(pack2(l0, l1), pack2(l2, l3));
        *(uint2*)(a2 + ab)        = hp;
        *(uint2*)(a2 + ab + 1024) = lp;
        *(uint2*)(a2 + ab + 2048) = hp;
    }
}

// ============================================================================
extern "C" void kernel_launch(void* const* d_in, const int* in_sizes, int n_in,
                              void* d_out, int out_size)
{
    const float* q    = (const float*)d_in[0];
    const float* k    = (const float*)d_in[1];
    const float* v    = (const float*)d_in[2];
    const int*   mask = (const int*)d_in[3];
    const float* Wq   = (const float*)d_in[4];
    const float* bq   = (const float*)d_in[5];
    const float* Wk   = (const float*)d_in[6];
    const float* bk   = (const float*)d_in[7];
    const float* Wv   = (const float*)d_in[8];
    const float* bv   = (const float*)d_in[9];
    const float* Wo   = (const float*)d_in[10];
    const float* bo   = (const float*)d_in[11];
    const float* g1   = (const float*)d_in[12];
    const float* b1   = (const float*)d_in[13];
    const float* g2   = (const float*)d_in[14];
    const float* b2   = (const float*)d_in[15];

    float *qp, *at, *x, *y, *mf;
    __nv_bfloat16 *aq, *ak, *av, *w2q, *w2k, *w2v, *w2o, *q2, *k2, *v2;
    cudaGetSymbolAddress((void**)&qp, g_qp);
    cudaGetSymbolAddress((void**)&at, g_att);
    cudaGetSymbolAddress((void**)&x,  g_x);
    cudaGetSymbolAddress((void**)&y,  g_y);
    cudaGetSymbolAddress((void**)&aq,  g_a2q);
    cudaGetSymbolAddress((void**)&ak,  g_a2k);
    cudaGetSymbolAddress((void**)&av,  g_a2v);
    cudaGetSymbolAddress((void**)&w2q, g_w2q);
    cudaGetSymbolAddress((void**)&w2k, g_w2k);
    cudaGetSymbolAddress((void**)&w2v, g_w2v);
    cudaGetSymbolAddress((void**)&w2o, g_w2o);
    cudaGetSymbolAddress((void**)&q2,  g_q2x);
    cudaGetSymbolAddress((void**)&k2,  g_k2x);
    cudaGetSymbolAddress((void**)&v2,  g_v2x);
    cudaGetSymbolAddress((void**)&mf,  g_mf);

    cudaFuncSetAttribute(gemm_qkv, cudaFuncAttributeMaxDynamicSharedMemorySize,
                         GEMM_SMEM);
    cudaFuncSetAttribute(gemm_o, cudaFuncAttributeMaxDynamicSharedMemorySize,
                         GEMM_SMEM);
    cudaFuncSetAttribute(flash_mma, cudaFuncAttributeMaxDynamicSharedMemorySize,
                         FLASH_SMEM);

    conv_w4<<<dim3(Dm / 32, Dm / 32, 4), dim3(32, 8)>>>(
        Wq, Wk, Wv, Wo, w2q, w2k, w2v, w2o);

    int cab4 = (int)(((size_t)NR * Dm) / 1024);   // vec4 grid
    conv_a3<<<dim3(cab4, 1, 3), 256>>>(q, k, v, aq, ak, av);
    conv_mask<<<(Bz * SKL + 255) / 256, 256>>>(mask, mf);

    gemm_qkv<<<dim3(Dm / 128, NR / 128, 3), 256, GEMM_SMEM>>>(
        aq, ak, av, w2q, w2k, w2v, bq, bk, bv, qp, q2, k2, v2);

    flash_mma<<<dim3(SQL / 128, Hh, Bz), 256, FLASH_SMEM>>>(q2, k2, v2, mf, at);

    add_ln<<<NR, 256>>>(qp, at, g1, b1, x, aq, 0);

    gemm_o<<<dim3(Dm / 128, NR / 128), 256, GEMM_SMEM>>>(aq, w2o, bo, y);

    add_ln<<<NR, 256>>>(x, y, g2, b2, (float*)d_out, (__nv_bfloat16*)0, 1);
}